// round 2
// baseline (speedup 1.0000x reference)
#include <cuda_runtime.h>

#define NN 50000
#define EE 800000
#define TT 24
#define ETOT (EE + NN)

typedef unsigned long long ull;

// ---------------- scratch ----------------
__device__ float g_h2last[NN * 64];
__device__ float g_xl[NN * 128];
__device__ float g_asrc[NN * 4];
__device__ float g_adst[NN * 4];
__device__ float g_max[NN * 4];
__device__ float g_denom[NN * 4];
__device__ float g_accum[NN * 128];
__device__ float g_ex[(long long)ETOT * 4];
__device__ float g_meansum;
__device__ float g_K[4];
__device__ int   g_idx64;

// ---------------- f32x2 helpers ----------------
__device__ __forceinline__ ull pack2(float a, float b) {
    ull r; asm("mov.b64 %0,{%1,%2};" : "=l"(r) : "f"(a), "f"(b)); return r;
}
__device__ __forceinline__ ull dup2(float a) {
    ull r; asm("mov.b64 %0,{%1,%1};" : "=l"(r) : "f"(a)); return r;
}
__device__ __forceinline__ void unpack2(ull v, float& a, float& b) {
    asm("mov.b64 {%0,%1},%2;" : "=f"(a), "=f"(b) : "l"(v));
}
__device__ __forceinline__ ull fma2(ull a, ull b, ull c) {
    ull d; asm("fma.rn.f32x2 %0,%1,%2,%3;" : "=l"(d) : "l"(a), "l"(b), "l"(c)); return d;
}
__device__ __forceinline__ float tanh_hw(float x) {
    float y; asm("tanh.approx.f32 %0,%1;" : "=f"(y) : "f"(x)); return y;
}
__device__ __forceinline__ float sig_hw(float x) {
    return fmaf(tanh_hw(0.5f * x), 0.5f, 0.5f);
}
__device__ __forceinline__ long long eidx(const void* ei, long long pos) {
    if (g_idx64) return ((const long long*)ei)[pos];
    return (long long)((const int*)ei)[pos];
}
__device__ __forceinline__ void atomicMaxF(float* addr, float val) {
    if (val >= 0.f) atomicMax((int*)addr, __float_as_int(val));
    else            atomicMin((unsigned int*)addr, __float_as_uint(val));
}

// ---------------- K0: init ----------------
__global__ void init_kernel(const float* __restrict__ lin_edge_w,
                            const float* __restrict__ att_edge) {
    long long stride = (long long)gridDim.x * blockDim.x;
    long long i0 = (long long)blockIdx.x * blockDim.x + threadIdx.x;
    for (long long i = i0; i < (long long)NN * 128; i += stride) g_accum[i] = 0.f;
    for (long long i = i0; i < (long long)NN * 4; i += stride) {
        g_denom[i] = 0.f;
        ((int*)g_max)[i] = 0xFF800000;
    }
    if (i0 == 0) g_meansum = 0.f;
    if (i0 < 4) {
        float s = 0.f;
        for (int c = 0; c < 32; c++) s += lin_edge_w[i0 * 32 + c] * att_edge[i0 * 32 + c];
        g_K[i0] = s;
    }
}

__global__ void detect_kernel(const long long* __restrict__ ei) {
    if (blockIdx.x == 0 && threadIdx.x == 0) {
        int ok = 1;
        for (int i = 0; i < 512; i++) {
            long long v = ei[i];
            if (v < 0 || v >= NN) { ok = 0; break; }
        }
        g_idx64 = ok;
    }
}

__global__ void mean_kernel(const float* __restrict__ ea) {
    __shared__ float red[256];
    float s = 0.f;
    for (long long i = (long long)blockIdx.x * blockDim.x + threadIdx.x; i < EE;
         i += (long long)gridDim.x * blockDim.x)
        s += ea[i];
    red[threadIdx.x] = s;
    __syncthreads();
    for (int o = 128; o; o >>= 1) {
        if (threadIdx.x < o) red[threadIdx.x] += red[threadIdx.x + o];
        __syncthreads();
    }
    if (threadIdx.x == 0) atomicAdd(&g_meansum, red[0]);
}

// ---------------- K2: fused 2-layer LSTM (f32x2 packed) ----------------
// 32 nodes/block, 256 threads. thread (ng, j): hidden unit j of nodes ng*8..ng*8+7.
// h stored transposed [unit k][node] with row stride 34 (8B-aligned node pairs,
// conflict-free: broadcast loads within warp, 2-way max on stores).
#define HSTR 34
__global__ void __launch_bounds__(256, 1) lstm_kernel(
    const float* __restrict__ x,
    const float* __restrict__ w_ih0, const float* __restrict__ w_hh0,
    const float* __restrict__ b_ih0, const float* __restrict__ b_hh0,
    const float* __restrict__ w_ih1, const float* __restrict__ w_hh1,
    const float* __restrict__ b_ih1, const float* __restrict__ b_hh1) {
    extern __shared__ float sm[];
    float* wT0   = sm;                  // [64][256]  w_hh0^T
    float* wTi1  = wT0 + 16384;         // [64][256]  w_ih1^T
    float* wTh1  = wTi1 + 16384;        // [64][256]  w_hh1^T
    float* bias0 = wTh1 + 16384;        // 256
    float* bias1 = bias0 + 256;         // 256
    float* wi0v  = bias1 + 256;         // 256
    float* h0T   = wi0v + 256;          // [64][HSTR]
    float* h1T   = h0T + 64 * HSTR;     // [64][HSTR]
    float* xs    = h1T + 64 * HSTR;     // [24][32]

    const int tid = threadIdx.x;
    for (int i = tid; i < 16384; i += 256) {
        int k = i >> 8, g = i & 255;
        wT0[i]  = w_hh0[g * 64 + k];
        wTi1[i] = w_ih1[g * 64 + k];
        wTh1[i] = w_hh1[g * 64 + k];
    }
    bias0[tid] = b_ih0[tid] + b_hh0[tid];
    bias1[tid] = b_ih1[tid] + b_hh1[tid];
    wi0v[tid]  = w_ih0[tid];
    for (int i = tid; i < TT * 32; i += 256) {
        int nl = i & 31, t = i >> 5;
        int node = blockIdx.x * 32 + nl;
        xs[t * 32 + nl] = (node < NN) ? x[node * 32 + 8 + t] : 0.f;
    }
    for (int i = tid; i < 64 * HSTR; i += 256) { h0T[i] = 0.f; h1T[i] = 0.f; }
    __syncthreads();

    const int j  = tid & 63;
    const int ng = tid >> 6;
    float c0[8], c1[8];
#pragma unroll
    for (int n = 0; n < 8; n++) { c0[n] = 0.f; c1[n] = 0.f; }

    const float bi0 = bias0[j], bf0 = bias0[64 + j], bg0 = bias0[128 + j], bo0 = bias0[192 + j];
    const float bi1 = bias1[j], bf1 = bias1[64 + j], bg1 = bias1[128 + j], bo1 = bias1[192 + j];
    const float wxi = wi0v[j], wxf = wi0v[64 + j], wxg = wi0v[128 + j], wxo = wi0v[192 + j];

    for (int t = 0; t < TT; t++) {
        // ================= layer 0 =================
        ull ai[4], af[4], ag[4], ao[4];
#pragma unroll
        for (int p = 0; p < 4; p++) { ai[p] = 0ULL; af[p] = 0ULL; ag[p] = 0ULL; ao[p] = 0ULL; }
#pragma unroll 2
        for (int k = 0; k < 64; k++) {
            const float* wr = wT0 + k * 256 + j;
            ull wi2 = dup2(wr[0]), wf2 = dup2(wr[64]), wg2 = dup2(wr[128]), wo2 = dup2(wr[192]);
            const ull* hp = (const ull*)(h0T + k * HSTR + ng * 8);
            ull hA = hp[0], hB = hp[1], hC = hp[2], hD = hp[3];
            ai[0] = fma2(wi2, hA, ai[0]); af[0] = fma2(wf2, hA, af[0]);
            ag[0] = fma2(wg2, hA, ag[0]); ao[0] = fma2(wo2, hA, ao[0]);
            ai[1] = fma2(wi2, hB, ai[1]); af[1] = fma2(wf2, hB, af[1]);
            ag[1] = fma2(wg2, hB, ag[1]); ao[1] = fma2(wo2, hB, ao[1]);
            ai[2] = fma2(wi2, hC, ai[2]); af[2] = fma2(wf2, hC, af[2]);
            ag[2] = fma2(wg2, hC, ag[2]); ao[2] = fma2(wo2, hC, ao[2]);
            ai[3] = fma2(wi2, hD, ai[3]); af[3] = fma2(wf2, hD, af[3]);
            ag[3] = fma2(wg2, hD, ag[3]); ao[3] = fma2(wo2, hD, ao[3]);
        }
        float hn[8];
#pragma unroll
        for (int p = 0; p < 4; p++) {
            float aiL, aiH, afL, afH, agL, agH, aoL, aoH;
            unpack2(ai[p], aiL, aiH); unpack2(af[p], afL, afH);
            unpack2(ag[p], agL, agH); unpack2(ao[p], aoL, aoH);
#pragma unroll
            for (int hh = 0; hh < 2; hh++) {
                int n = 2 * p + hh;
                float av = hh ? aiH : aiL, fv = hh ? afH : afL;
                float gv = hh ? agH : agL, ov = hh ? aoH : aoL;
                float xv = xs[t * 32 + ng * 8 + n];
                float gi = av + fmaf(xv, wxi, bi0);
                float gf = fv + fmaf(xv, wxf, bf0);
                float gg = gv + fmaf(xv, wxg, bg0);
                float go = ov + fmaf(xv, wxo, bo0);
                float ct = sig_hw(gf) * c0[n] + sig_hw(gi) * tanh_hw(gg);
                c0[n] = ct;
                hn[n] = sig_hw(go) * tanh_hw(ct);
            }
        }
        __syncthreads();
        {
            ull* hw = (ull*)(h0T + j * HSTR + ng * 8);
            hw[0] = pack2(hn[0], hn[1]); hw[1] = pack2(hn[2], hn[3]);
            hw[2] = pack2(hn[4], hn[5]); hw[3] = pack2(hn[6], hn[7]);
        }
        __syncthreads();

        // ================= layer 1 =================
#pragma unroll
        for (int p = 0; p < 4; p++) { ai[p] = 0ULL; af[p] = 0ULL; ag[p] = 0ULL; ao[p] = 0ULL; }
#pragma unroll 2
        for (int k = 0; k < 64; k++) {
            const float* wr = wTi1 + k * 256 + j;
            ull wi2 = dup2(wr[0]), wf2 = dup2(wr[64]), wg2 = dup2(wr[128]), wo2 = dup2(wr[192]);
            const ull* hp = (const ull*)(h0T + k * HSTR + ng * 8);
            ull hA = hp[0], hB = hp[1], hC = hp[2], hD = hp[3];
            ai[0] = fma2(wi2, hA, ai[0]); af[0] = fma2(wf2, hA, af[0]);
            ag[0] = fma2(wg2, hA, ag[0]); ao[0] = fma2(wo2, hA, ao[0]);
            ai[1] = fma2(wi2, hB, ai[1]); af[1] = fma2(wf2, hB, af[1]);
            ag[1] = fma2(wg2, hB, ag[1]); ao[1] = fma2(wo2, hB, ao[1]);
            ai[2] = fma2(wi2, hC, ai[2]); af[2] = fma2(wf2, hC, af[2]);
            ag[2] = fma2(wg2, hC, ag[2]); ao[2] = fma2(wo2, hC, ao[2]);
            ai[3] = fma2(wi2, hD, ai[3]); af[3] = fma2(wf2, hD, af[3]);
            ag[3] = fma2(wg2, hD, ag[3]); ao[3] = fma2(wo2, hD, ao[3]);
        }
#pragma unroll 2
        for (int k = 0; k < 64; k++) {
            const float* wr = wTh1 + k * 256 + j;
            ull wi2 = dup2(wr[0]), wf2 = dup2(wr[64]), wg2 = dup2(wr[128]), wo2 = dup2(wr[192]);
            const ull* hp = (const ull*)(h1T + k * HSTR + ng * 8);
            ull hA = hp[0], hB = hp[1], hC = hp[2], hD = hp[3];
            ai[0] = fma2(wi2, hA, ai[0]); af[0] = fma2(wf2, hA, af[0]);
            ag[0] = fma2(wg2, hA, ag[0]); ao[0] = fma2(wo2, hA, ao[0]);
            ai[1] = fma2(wi2, hB, ai[1]); af[1] = fma2(wf2, hB, af[1]);
            ag[1] = fma2(wg2, hB, ag[1]); ao[1] = fma2(wo2, hB, ao[1]);
            ai[2] = fma2(wi2, hC, ai[2]); af[2] = fma2(wf2, hC, af[2]);
            ag[2] = fma2(wg2, hC, ag[2]); ao[2] = fma2(wo2, hC, ao[2]);
            ai[3] = fma2(wi2, hD, ai[3]); af[3] = fma2(wf2, hD, af[3]);
            ag[3] = fma2(wg2, hD, ag[3]); ao[3] = fma2(wo2, hD, ao[3]);
        }
#pragma unroll
        for (int p = 0; p < 4; p++) {
            float aiL, aiH, afL, afH, agL, agH, aoL, aoH;
            unpack2(ai[p], aiL, aiH); unpack2(af[p], afL, afH);
            unpack2(ag[p], agL, agH); unpack2(ao[p], aoL, aoH);
#pragma unroll
            for (int hh = 0; hh < 2; hh++) {
                int n = 2 * p + hh;
                float av = hh ? aiH : aiL, fv = hh ? afH : afL;
                float gv = hh ? agH : agL, ov = hh ? aoH : aoL;
                float gi = av + bi1;
                float gf = fv + bf1;
                float gg = gv + bg1;
                float go = ov + bo1;
                float ct = sig_hw(gf) * c1[n] + sig_hw(gi) * tanh_hw(gg);
                c1[n] = ct;
                hn[n] = sig_hw(go) * tanh_hw(ct);
            }
        }
        __syncthreads();
        {
            ull* hw = (ull*)(h1T + j * HSTR + ng * 8);
            hw[0] = pack2(hn[0], hn[1]); hw[1] = pack2(hn[2], hn[3]);
            hw[2] = pack2(hn[4], hn[5]); hw[3] = pack2(hn[6], hn[7]);
        }
        __syncthreads();
    }

    for (int i = tid; i < 32 * 64; i += 256) {
        int node = blockIdx.x * 32 + (i >> 6), k = i & 63;
        if (node < NN) g_h2last[node * 64 + k] = h1T[k * HSTR + (i >> 6)];
    }
}

// ---------------- K3: xl = combined @ lin_w^T ; a_src, a_dst ----------------
__global__ void node_feat_kernel(const float* __restrict__ x,
                                 const float* __restrict__ lin_w,
                                 const float* __restrict__ att_src,
                                 const float* __restrict__ att_dst) {
    __shared__ float sW[72 * 128];
    __shared__ float scomb[8][72];
    __shared__ float ssrc[128], sdst[128];
    int tid = threadIdx.x;
    for (int i = tid; i < 72 * 128; i += 256) {
        int d = i >> 7, g = i & 127;
        sW[i] = lin_w[g * 72 + d];
    }
    if (tid < 128) { ssrc[tid] = att_src[tid]; sdst[tid] = att_dst[tid]; }
    int nl = tid >> 5, lane = tid & 31;
    int node = blockIdx.x * 8 + nl;
    for (int d = lane; d < 72; d += 32)
        scomb[nl][d] = (node < NN) ? (d < 64 ? g_h2last[node * 64 + d]
                                             : x[node * 32 + (d - 64)])
                                   : 0.f;
    __syncthreads();
    float o0 = 0.f, o1 = 0.f, o2 = 0.f, o3 = 0.f;
    for (int d = 0; d < 72; d++) {
        float cv = scomb[nl][d];
        const float4 w4 = *(const float4*)&sW[d * 128 + lane * 4];
        o0 += cv * w4.x; o1 += cv * w4.y; o2 += cv * w4.z; o3 += cv * w4.w;
    }
    float ps = o0 * ssrc[lane * 4] + o1 * ssrc[lane * 4 + 1] +
               o2 * ssrc[lane * 4 + 2] + o3 * ssrc[lane * 4 + 3];
    float pd = o0 * sdst[lane * 4] + o1 * sdst[lane * 4 + 1] +
               o2 * sdst[lane * 4 + 2] + o3 * sdst[lane * 4 + 3];
    for (int off = 4; off; off >>= 1) {
        ps += __shfl_down_sync(0xffffffffu, ps, off, 8);
        pd += __shfl_down_sync(0xffffffffu, pd, off, 8);
    }
    if (node < NN) {
        *(float4*)&g_xl[node * 128 + lane * 4] = make_float4(o0, o1, o2, o3);
        if ((lane & 7) == 0) {
            int h = lane >> 3;
            g_asrc[node * 4 + h] = ps;
            g_adst[node * 4 + h] = pd;
        }
    }
}

// ---------------- per-edge logit ----------------
__device__ __forceinline__ void edge_logits(const void* ei, const float* ea,
                                            long long e, long long& s, long long& d,
                                            float lg[4]) {
    float a;
    if (e < EE) {
        s = eidx(ei, e);
        d = eidx(ei, (long long)EE + e);
        a = ea[e];
    } else {
        s = d = e - EE;
        a = g_meansum * (1.f / EE);
    }
    const float4 as = *(const float4*)&g_asrc[s * 4];
    const float4 ad = *(const float4*)&g_adst[d * 4];
    const float4 Kv = *(const float4*)g_K;
    lg[0] = as.x + ad.x + a * Kv.x;
    lg[1] = as.y + ad.y + a * Kv.y;
    lg[2] = as.z + ad.z + a * Kv.z;
    lg[3] = as.w + ad.w + a * Kv.w;
#pragma unroll
    for (int h = 0; h < 4; h++) lg[h] = lg[h] > 0.f ? lg[h] : 0.2f * lg[h];
}

// ---------------- K4: segment max ----------------
__global__ void logit_max_kernel(const void* __restrict__ ei, const float* __restrict__ ea) {
    long long e = (long long)blockIdx.x * blockDim.x + threadIdx.x;
    if (e >= ETOT) return;
    long long s, d;
    float lg[4];
    edge_logits(ei, ea, e, s, d, lg);
#pragma unroll
    for (int h = 0; h < 4; h++) atomicMaxF(&g_max[d * 4 + h], lg[h]);
}

// ---------------- K5: ex + denom (vector red) ----------------
__global__ void softmax_kernel(const void* __restrict__ ei, const float* __restrict__ ea) {
    long long e = (long long)blockIdx.x * blockDim.x + threadIdx.x;
    if (e >= ETOT) return;
    long long s, d;
    float lg[4];
    edge_logits(ei, ea, e, s, d, lg);
    const float4 mv = *(const float4*)&g_max[d * 4];
    float e0 = __expf(lg[0] - mv.x);
    float e1 = __expf(lg[1] - mv.y);
    float e2 = __expf(lg[2] - mv.z);
    float e3 = __expf(lg[3] - mv.w);
    *(float4*)&g_ex[e * 4] = make_float4(e0, e1, e2, e3);
    float* dptr = &g_denom[d * 4];
    asm volatile("red.global.add.v4.f32 [%0], {%1,%2,%3,%4};"
                 :: "l"(dptr), "f"(e0), "f"(e1), "f"(e2), "f"(e3) : "memory");
}

// ---------------- K6: message scatter (alpha fused, vector red) ----------------
__global__ void message_kernel(const void* __restrict__ ei) {
    long long idx = (long long)blockIdx.x * blockDim.x + threadIdx.x;
    long long e = idx >> 5;
    int lane = (int)(idx & 31);
    if (e >= ETOT) return;
    long long s, d;
    if (e < EE) {
        s = eidx(ei, e);
        d = eidx(ei, (long long)EE + e);
    } else {
        s = d = e - EE;
    }
    int h = lane >> 3;
    float ex = g_ex[e * 4 + h];
    float dn = g_denom[d * 4 + h];
    float al = ex / (dn + 1e-16f);
    float4 xv = ((const float4*)(g_xl + s * 128))[lane];
    float* dst = g_accum + d * 128 + lane * 4;
    asm volatile("red.global.add.v4.f32 [%0], {%1,%2,%3,%4};"
                 :: "l"(dst), "f"(xv.x * al), "f"(xv.y * al),
                    "f"(xv.z * al), "f"(xv.w * al) : "memory");
}

// ---------------- K7: bias + elu + fc + relu ----------------
__global__ void out_kernel(const float* __restrict__ gat_bias,
                           const float* __restrict__ fc_w,
                           const float* __restrict__ fc_b,
                           float* __restrict__ out) {
    long long idx = (long long)blockIdx.x * blockDim.x + threadIdx.x;
    int node = (int)(idx >> 5), lane = (int)(idx & 31);
    if (node >= NN) return;
    float a0 = 0.f, a1 = 0.f, a2 = 0.f, a3 = 0.f;
    const float4 av = *(const float4*)&g_accum[node * 128 + lane * 4];
    const float4 bv = *(const float4*)&gat_bias[lane * 4];
    float v[4] = {av.x + bv.x, av.y + bv.y, av.z + bv.z, av.w + bv.w};
#pragma unroll
    for (int r = 0; r < 4; r++) {
        float vv = v[r] > 0.f ? v[r] : expm1f(v[r]);
        int hc = lane * 4 + r;
        a0 += vv * fc_w[0 * 128 + hc];
        a1 += vv * fc_w[1 * 128 + hc];
        a2 += vv * fc_w[2 * 128 + hc];
        a3 += vv * fc_w[3 * 128 + hc];
    }
    for (int off = 16; off; off >>= 1) {
        a0 += __shfl_down_sync(0xffffffffu, a0, off);
        a1 += __shfl_down_sync(0xffffffffu, a1, off);
        a2 += __shfl_down_sync(0xffffffffu, a2, off);
        a3 += __shfl_down_sync(0xffffffffu, a3, off);
    }
    if (lane == 0) {
        out[node * 4 + 0] = fmaxf(a0 + fc_b[0], 0.f);
        out[node * 4 + 1] = fmaxf(a1 + fc_b[1], 0.f);
        out[node * 4 + 2] = fmaxf(a2 + fc_b[2], 0.f);
        out[node * 4 + 3] = fmaxf(a3 + fc_b[3], 0.f);
    }
}

// ---------------- launch ----------------
extern "C" void kernel_launch(void* const* d_in, const int* in_sizes, int n_in,
                              void* d_out, int out_size) {
    const float* x        = (const float*)d_in[0];
    const void*  ei       = d_in[1];
    const float* ea       = (const float*)d_in[2];
    const float* w_ih0    = (const float*)d_in[3];
    const float* w_hh0    = (const float*)d_in[4];
    const float* b_ih0    = (const float*)d_in[5];
    const float* b_hh0    = (const float*)d_in[6];
    const float* w_ih1    = (const float*)d_in[7];
    const float* w_hh1    = (const float*)d_in[8];
    const float* b_ih1    = (const float*)d_in[9];
    const float* b_hh1    = (const float*)d_in[10];
    const float* lin_w    = (const float*)d_in[11];
    const float* lin_ew   = (const float*)d_in[12];
    const float* att_src  = (const float*)d_in[13];
    const float* att_dst  = (const float*)d_in[14];
    const float* att_edge = (const float*)d_in[15];
    const float* gat_bias = (const float*)d_in[16];
    const float* fc_w     = (const float*)d_in[17];
    const float* fc_b     = (const float*)d_in[18];
    float* out = (float*)d_out;

    const int lstm_smem =
        (3 * 16384 + 3 * 256 + 2 * 64 * HSTR + TT * 32) * (int)sizeof(float);
    cudaFuncSetAttribute(lstm_kernel, cudaFuncAttributeMaxDynamicSharedMemorySize, lstm_smem);

    init_kernel<<<2048, 256>>>(lin_ew, att_edge);
    detect_kernel<<<1, 32>>>((const long long*)ei);
    mean_kernel<<<256, 256>>>(ea);
    lstm_kernel<<<(NN + 31) / 32, 256, lstm_smem>>>(x, w_ih0, w_hh0, b_ih0, b_hh0,
                                                    w_ih1, w_hh1, b_ih1, b_hh1);
    node_feat_kernel<<<(NN + 7) / 8, 256>>>(x, lin_w, att_src, att_dst);
    logit_max_kernel<<<(ETOT + 255) / 256, 256>>>(ei, ea);
    softmax_kernel<<<(ETOT + 255) / 256, 256>>>(ei, ea);
    message_kernel<<<(int)(((long long)ETOT * 32 + 255) / 256), 256>>>(ei);
    out_kernel<<<(NN * 32 + 255) / 256, 256>>>(gat_bias, fc_w, fc_b, out);
}

// round 4
// speedup vs baseline: 2.7888x; 2.7888x over previous
#include <cuda_runtime.h>
#include <cuda_bf16.h>
#include <stdint.h>

#define NN 50000
#define EE 800000
#define TT 24
#define ETOT (EE + NN)

// ---------------- scratch ----------------
__device__ float g_h2last[NN * 64];
__device__ float g_xl[NN * 128];
__device__ float g_asrc[NN * 4];
__device__ float g_adst[NN * 4];
__device__ float g_max[NN * 4];
__device__ float g_denom[NN * 4];
__device__ float g_accum[NN * 128];
__device__ float g_ex[(long long)ETOT * 4];
__device__ float g_meansum;
__device__ float g_K[4];
__device__ int   g_idx64;

// ---------------- helpers ----------------
__device__ __forceinline__ float tanh_hw(float x) {
    float y; asm("tanh.approx.f32 %0,%1;" : "=f"(y) : "f"(x)); return y;
}
__device__ __forceinline__ float sig_hw(float x) {
    return fmaf(tanh_hw(0.5f * x), 0.5f, 0.5f);
}
__device__ __forceinline__ long long eidx(const void* ei, long long pos) {
    if (g_idx64) return ((const long long*)ei)[pos];
    return (long long)((const int*)ei)[pos];
}
__device__ __forceinline__ void atomicMaxF(float* addr, float val) {
    if (val >= 0.f) atomicMax((int*)addr, __float_as_int(val));
    else            atomicMin((unsigned int*)addr, __float_as_uint(val));
}
__device__ __forceinline__ uint32_t smem_u32(const void* p) {
    uint32_t a;
    asm("{ .reg .u64 t; cvta.to.shared.u64 t, %1; cvt.u32.u64 %0, t; }"
        : "=r"(a) : "l"(p));
    return a;
}
__device__ __forceinline__ void ldsm4(uint32_t* r, uint32_t addr) {
    asm volatile("ldmatrix.sync.aligned.m8n8.x4.shared.b16 {%0,%1,%2,%3}, [%4];"
                 : "=r"(r[0]), "=r"(r[1]), "=r"(r[2]), "=r"(r[3]) : "r"(addr));
}
__device__ __forceinline__ void mma16816(float* d, const uint32_t* a, const uint32_t* b) {
    asm volatile(
        "mma.sync.aligned.m16n8k16.row.col.f32.bf16.bf16.f32 "
        "{%0,%1,%2,%3}, {%4,%5,%6,%7}, {%8,%9}, {%0,%1,%2,%3};"
        : "+f"(d[0]), "+f"(d[1]), "+f"(d[2]), "+f"(d[3])
        : "r"(a[0]), "r"(a[1]), "r"(a[2]), "r"(a[3]), "r"(b[0]), "r"(b[1]));
}
__device__ __forceinline__ void packpair(float a, float b, uint32_t& hi, uint32_t& lo) {
    asm("cvt.rn.bf16x2.f32 %0,%1,%2;" : "=r"(hi) : "f"(b), "f"(a));
    float ra = a - __uint_as_float(hi << 16);
    float rb = b - __uint_as_float(hi & 0xffff0000u);
    asm("cvt.rn.bf16x2.f32 %0,%1,%2;" : "=r"(lo) : "f"(rb), "f"(ra));
}

// ---------------- SMEM layout (bytes) ----------------
#define OFF_WCH 0          // Wcat hi [256 rows][256B]  (k<64: w_ih1, k>=64: w_hh1)
#define OFF_WCL 65536      // Wcat lo
#define OFF_HHI 131072     // h hi [128 rows][256B]  (chunks 0-7: h0, 8-15: h1)
#define OFF_HLO 163840     // h lo
#define OFF_XS  196608     // float[24*128]
#define OFF_WB  208896     // float[768]: w_ih0 | b0 | b1
#define LSTM_DSMEM (211968 + 1024)

// swizzled offsets
__device__ __forceinline__ uint32_t h_off(int row, int chunk, int tg) {
    return (uint32_t)(row * 256 + (((chunk ^ (row & 7)) << 4)) + (tg << 2));
}
__device__ __forceinline__ uint32_t a_off(int mt, int kt, int lane) {
    int tile = lane >> 3, lr = lane & 7;
    int row = mt * 16 + ((tile & 1) << 3) + lr;
    int chunk = 2 * kt + (tile >> 1);
    return (uint32_t)(row * 256 + ((chunk ^ (row & 7)) << 4));
}
__device__ __forceinline__ uint32_t b_off(int w, int gt, int kt2, int lane) {
    int q = lane >> 3, lr = lane & 7;
    int row = gt * 64 + w * 8 + lr;
    int chunk = 2 * kt2 + q;
    return (uint32_t)(row * 256 + ((chunk ^ (row & 7)) << 4));
}
__device__ __forceinline__ uint32_t w0_off(int w, int gt, int kt2, int lane) {
    int q = lane >> 3, lr = lane & 7;
    int row = gt * 64 + w * 8 + lr;
    int chunk = 2 * kt2 + q;
    return (uint32_t)(row * 128 + ((chunk ^ (row & 7)) << 4));
}

// ---------------- K0: init ----------------
__global__ void init_kernel(const float* __restrict__ lin_edge_w,
                            const float* __restrict__ att_edge) {
    long long stride = (long long)gridDim.x * blockDim.x;
    long long i0 = (long long)blockIdx.x * blockDim.x + threadIdx.x;
    for (long long i = i0; i < (long long)NN * 128; i += stride) g_accum[i] = 0.f;
    for (long long i = i0; i < (long long)NN * 4; i += stride) {
        g_denom[i] = 0.f;
        ((int*)g_max)[i] = 0xFF800000;
    }
    if (i0 == 0) g_meansum = 0.f;
    if (i0 < 4) {
        float s = 0.f;
        for (int c = 0; c < 32; c++) s += lin_edge_w[i0 * 32 + c] * att_edge[i0 * 32 + c];
        g_K[i0] = s;
    }
}

__global__ void detect_kernel(const long long* __restrict__ ei) {
    if (blockIdx.x == 0 && threadIdx.x == 0) {
        int ok = 1;
        for (int i = 0; i < 512; i++) {
            long long v = ei[i];
            if (v < 0 || v >= NN) { ok = 0; break; }
        }
        g_idx64 = ok;
    }
}

__global__ void mean_kernel(const float* __restrict__ ea) {
    __shared__ float red[256];
    float s = 0.f;
    for (long long i = (long long)blockIdx.x * blockDim.x + threadIdx.x; i < EE;
         i += (long long)gridDim.x * blockDim.x)
        s += ea[i];
    red[threadIdx.x] = s;
    __syncthreads();
    for (int o = 128; o; o >>= 1) {
        if (threadIdx.x < o) red[threadIdx.x] += red[threadIdx.x + o];
        __syncthreads();
    }
    if (threadIdx.x == 0) atomicAdd(&g_meansum, red[0]);
}

// ---------------- K2: HMMA fused 2-layer LSTM ----------------
// 128 nodes/CTA, 8 warps. Warp w: j in [8w, 8w+8) for all 4 gates, all nodes.
// bf16 hi/lo split, 3 MMA products per logical matmul -> fp32-level precision.
__global__ void __launch_bounds__(256, 1) lstm_mma_kernel(
    const float* __restrict__ x,
    const float* __restrict__ w_ih0, const float* __restrict__ w_hh0,
    const float* __restrict__ b_ih0, const float* __restrict__ b_hh0,
    const float* __restrict__ w_ih1, const float* __restrict__ w_hh1,
    const float* __restrict__ b_ih1, const float* __restrict__ b_hh1)
{
    extern __shared__ char dsm_raw[];
    char* dsm = (char*)(((unsigned long long)dsm_raw + 1023ULL) & ~1023ULL);
    const uint32_t smb = smem_u32(dsm);

    const int tid = threadIdx.x;
    const int w = tid >> 5, lane = tid & 31;
    const int tg = lane & 3, gg = lane >> 2;
    const int nodeBase = blockIdx.x * 128;

    float* xs  = (float*)(dsm + OFF_XS);
    float* wbp = (float*)(dsm + OFF_WB);

    // ---- fill Wcat (w_ih1 | w_hh1) hi/lo, swizzled ----
    for (int i = tid; i < 256 * 128; i += 256) {
        int n = i >> 7, k = i & 127;
        float v = (k < 64) ? w_ih1[n * 64 + k] : w_hh1[n * 64 + (k - 64)];
        __nv_bfloat16 hb = __float2bfloat16(v);
        float lo = v - __bfloat162float(hb);
        uint32_t off = (uint32_t)(n * 256 + (((k >> 3) ^ (n & 7)) << 4) + ((k & 7) << 1));
        *(__nv_bfloat16*)(dsm + OFF_WCH + off) = hb;
        *(__nv_bfloat16*)(dsm + OFF_WCL + off) = __float2bfloat16(lo);
    }
    // ---- stage W0 (w_hh0) hi/lo into the h arrays (temporarily) ----
    for (int i = tid; i < 256 * 64; i += 256) {
        int n = i >> 6, k = i & 63;
        float v = w_hh0[n * 64 + k];
        __nv_bfloat16 hb = __float2bfloat16(v);
        float lo = v - __bfloat162float(hb);
        uint32_t off = (uint32_t)(n * 128 + (((k >> 3) ^ (n & 7)) << 4) + ((k & 7) << 1));
        *(__nv_bfloat16*)(dsm + OFF_HHI + off) = hb;
        *(__nv_bfloat16*)(dsm + OFF_HLO + off) = __float2bfloat16(lo);
    }
    // ---- x slice + fused consts ----
    for (int i = tid; i < TT * 128; i += 256) {
        int t = i >> 7, nl = i & 127;
        int nd = nodeBase + nl;
        xs[i] = (nd < NN) ? x[nd * 32 + 8 + t] : 0.f;
    }
    if (tid < 256) {
        wbp[tid]       = w_ih0[tid];
        wbp[256 + tid] = b_ih0[tid] + b_hh0[tid];
        wbp[512 + tid] = b_ih1[tid] + b_hh1[tid];
    }
    __syncthreads();

    // ---- W0 fragments -> registers ----
    uint32_t w0h[4][4][2], w0l[4][4][2];
#pragma unroll
    for (int gt = 0; gt < 4; gt++)
#pragma unroll
        for (int kt2 = 0; kt2 < 4; kt2 += 2) {
            uint32_t r[4];
            ldsm4(r, smb + OFF_HHI + w0_off(w, gt, kt2, lane));
            w0h[gt][kt2][0] = r[0]; w0h[gt][kt2][1] = r[1];
            w0h[gt][kt2 + 1][0] = r[2]; w0h[gt][kt2 + 1][1] = r[3];
            ldsm4(r, smb + OFF_HLO + w0_off(w, gt, kt2, lane));
            w0l[gt][kt2][0] = r[0]; w0l[gt][kt2][1] = r[1];
            w0l[gt][kt2 + 1][0] = r[2]; w0l[gt][kt2 + 1][1] = r[3];
        }
    // per-thread consts
    const int jj0 = w * 8 + (tg << 1);
    float cwx[4][2], cb0[4][2], cb1[4][2];
#pragma unroll
    for (int gt = 0; gt < 4; gt++)
#pragma unroll
        for (int e = 0; e < 2; e++) {
            int jg = gt * 64 + jj0 + e;
            cwx[gt][e] = wbp[jg];
            cb0[gt][e] = wbp[256 + jg];
            cb1[gt][e] = wbp[512 + jg];
        }
    __syncthreads();

    // ---- zero h arrays ----
    for (int i = tid; i < 32768 / 4; i += 256) {
        ((uint32_t*)(dsm + OFF_HHI))[i] = 0u;
        ((uint32_t*)(dsm + OFF_HLO))[i] = 0u;
    }
    __syncthreads();

    float c0[32], c1[32];
#pragma unroll
    for (int i = 0; i < 32; i++) { c0[i] = 0.f; c1[i] = 0.f; }
    uint32_t stash[32];

#pragma unroll 1
    for (int t = 0; t < TT; t++) {
        // ============ layer 0 ============
#pragma unroll
        for (int mt = 0; mt < 8; mt++) {
            float acc[16];
#pragma unroll
            for (int i = 0; i < 16; i++) acc[i] = 0.f;
#pragma unroll
            for (int kt = 0; kt < 4; kt++) {
                uint32_t Ah[4], Al[4];
                ldsm4(Ah, smb + OFF_HHI + a_off(mt, kt, lane));
                ldsm4(Al, smb + OFF_HLO + a_off(mt, kt, lane));
#pragma unroll
                for (int gt = 0; gt < 4; gt++) {
                    mma16816(&acc[gt * 4], Ah, w0h[gt][kt]);
                    mma16816(&acc[gt * 4], Al, w0h[gt][kt]);
                    mma16816(&acc[gt * 4], Ah, w0l[gt][kt]);
                }
            }
            int r0 = mt * 16 + gg;
            float x0 = xs[t * 128 + r0], x1 = xs[t * 128 + r0 + 8];
            float hv[4];
#pragma unroll
            for (int q = 0; q < 4; q++) {
                int e = q & 1;
                float xv = (q >> 1) ? x1 : x0;
                float gi = acc[q]      + fmaf(xv, cwx[0][e], cb0[0][e]);
                float gf = acc[4 + q]  + fmaf(xv, cwx[1][e], cb0[1][e]);
                float gG = acc[8 + q]  + fmaf(xv, cwx[2][e], cb0[2][e]);
                float go = acc[12 + q] + fmaf(xv, cwx[3][e], cb0[3][e]);
                float c = sig_hw(gf) * c0[mt * 4 + q] + sig_hw(gi) * tanh_hw(gG);
                c0[mt * 4 + q] = c;
                hv[q] = sig_hw(go) * tanh_hw(c);
            }
            packpair(hv[0], hv[1], stash[mt * 4 + 0], stash[mt * 4 + 1]);
            packpair(hv[2], hv[3], stash[mt * 4 + 2], stash[mt * 4 + 3]);
        }
        __syncthreads();
#pragma unroll
        for (int mt = 0; mt < 8; mt++) {
            int r0 = mt * 16 + gg;
            *(uint32_t*)(dsm + OFF_HHI + h_off(r0, w, tg))     = stash[mt * 4 + 0];
            *(uint32_t*)(dsm + OFF_HLO + h_off(r0, w, tg))     = stash[mt * 4 + 1];
            *(uint32_t*)(dsm + OFF_HHI + h_off(r0 + 8, w, tg)) = stash[mt * 4 + 2];
            *(uint32_t*)(dsm + OFF_HLO + h_off(r0 + 8, w, tg)) = stash[mt * 4 + 3];
        }
        __syncthreads();

        // ============ layer 1 (K=128 cat: Wi1|Wh1 x h0new;h1) ============
#pragma unroll
        for (int mt = 0; mt < 8; mt++) {
            float acc[16];
#pragma unroll
            for (int i = 0; i < 16; i++) acc[i] = 0.f;
#pragma unroll
            for (int kt2 = 0; kt2 < 8; kt2 += 2) {
                uint32_t Bh[4][4], Bl[4][4];
#pragma unroll
                for (int gt = 0; gt < 4; gt++) {
                    ldsm4(Bh[gt], smb + OFF_WCH + b_off(w, gt, kt2, lane));
                    ldsm4(Bl[gt], smb + OFF_WCL + b_off(w, gt, kt2, lane));
                }
#pragma unroll
                for (int dk = 0; dk < 2; dk++) {
                    uint32_t Ah[4], Al[4];
                    ldsm4(Ah, smb + OFF_HHI + a_off(mt, kt2 + dk, lane));
                    ldsm4(Al, smb + OFF_HLO + a_off(mt, kt2 + dk, lane));
#pragma unroll
                    for (int gt = 0; gt < 4; gt++) {
                        mma16816(&acc[gt * 4], Ah, &Bh[gt][dk * 2]);
                        mma16816(&acc[gt * 4], Al, &Bh[gt][dk * 2]);
                        mma16816(&acc[gt * 4], Ah, &Bl[gt][dk * 2]);
                    }
                }
            }
            int r0 = mt * 16 + gg;
            float hv[4];
#pragma unroll
            for (int q = 0; q < 4; q++) {
                int e = q & 1;
                float gi = acc[q]      + cb1[0][e];
                float gf = acc[4 + q]  + cb1[1][e];
                float gG = acc[8 + q]  + cb1[2][e];
                float go = acc[12 + q] + cb1[3][e];
                float c = sig_hw(gf) * c1[mt * 4 + q] + sig_hw(gi) * tanh_hw(gG);
                c1[mt * 4 + q] = c;
                hv[q] = sig_hw(go) * tanh_hw(c);
            }
            if (t == TT - 1) {
                int nd0 = nodeBase + r0, nd1 = nd0 + 8;
                if (nd0 < NN) *(float2*)&g_h2last[nd0 * 64 + jj0] = make_float2(hv[0], hv[1]);
                if (nd1 < NN) *(float2*)&g_h2last[nd1 * 64 + jj0] = make_float2(hv[2], hv[3]);
            } else {
                packpair(hv[0], hv[1], stash[mt * 4 + 0], stash[mt * 4 + 1]);
                packpair(hv[2], hv[3], stash[mt * 4 + 2], stash[mt * 4 + 3]);
            }
        }
        if (t < TT - 1) {
            __syncthreads();
#pragma unroll
            for (int mt = 0; mt < 8; mt++) {
                int r0 = mt * 16 + gg;
                *(uint32_t*)(dsm + OFF_HHI + h_off(r0, 8 + w, tg))     = stash[mt * 4 + 0];
                *(uint32_t*)(dsm + OFF_HLO + h_off(r0, 8 + w, tg))     = stash[mt * 4 + 1];
                *(uint32_t*)(dsm + OFF_HHI + h_off(r0 + 8, 8 + w, tg)) = stash[mt * 4 + 2];
                *(uint32_t*)(dsm + OFF_HLO + h_off(r0 + 8, 8 + w, tg)) = stash[mt * 4 + 3];
            }
            __syncthreads();
        }
    }
}

// ---------------- K3: xl = combined @ lin_w^T ; a_src, a_dst ----------------
__global__ void node_feat_kernel(const float* __restrict__ x,
                                 const float* __restrict__ lin_w,
                                 const float* __restrict__ att_src,
                                 const float* __restrict__ att_dst) {
    __shared__ float sW[72 * 128];
    __shared__ float scomb[8][72];
    __shared__ float ssrc[128], sdst[128];
    int tid = threadIdx.x;
    for (int i = tid; i < 72 * 128; i += 256) {
        int d = i >> 7, g = i & 127;
        sW[i] = lin_w[g * 72 + d];
    }
    if (tid < 128) { ssrc[tid] = att_src[tid]; sdst[tid] = att_dst[tid]; }
    int nl = tid >> 5, lane = tid & 31;
    int node = blockIdx.x * 8 + nl;
    for (int d = lane; d < 72; d += 32)
        scomb[nl][d] = (node < NN) ? (d < 64 ? g_h2last[node * 64 + d]
                                             : x[node * 32 + (d - 64)])
                                   : 0.f;
    __syncthreads();
    float o0 = 0.f, o1 = 0.f, o2 = 0.f, o3 = 0.f;
    for (int d = 0; d < 72; d++) {
        float cv = scomb[nl][d];
        const float4 w4 = *(const float4*)&sW[d * 128 + lane * 4];
        o0 += cv * w4.x; o1 += cv * w4.y; o2 += cv * w4.z; o3 += cv * w4.w;
    }
    float ps = o0 * ssrc[lane * 4] + o1 * ssrc[lane * 4 + 1] +
               o2 * ssrc[lane * 4 + 2] + o3 * ssrc[lane * 4 + 3];
    float pd = o0 * sdst[lane * 4] + o1 * sdst[lane * 4 + 1] +
               o2 * sdst[lane * 4 + 2] + o3 * sdst[lane * 4 + 3];
    for (int off = 4; off; off >>= 1) {
        ps += __shfl_down_sync(0xffffffffu, ps, off, 8);
        pd += __shfl_down_sync(0xffffffffu, pd, off, 8);
    }
    if (node < NN) {
        *(float4*)&g_xl[node * 128 + lane * 4] = make_float4(o0, o1, o2, o3);
        if ((lane & 7) == 0) {
            int h = lane >> 3;
            g_asrc[node * 4 + h] = ps;
            g_adst[node * 4 + h] = pd;
        }
    }
}

// ---------------- per-edge logit ----------------
__device__ __forceinline__ void edge_logits(const void* ei, const float* ea,
                                            long long e, long long& s, long long& d,
                                            float lg[4]) {
    float a;
    if (e < EE) {
        s = eidx(ei, e);
        d = eidx(ei, (long long)EE + e);
        a = ea[e];
    } else {
        s = d = e - EE;
        a = g_meansum * (1.f / EE);
    }
    const float4 as = *(const float4*)&g_asrc[s * 4];
    const float4 ad = *(const float4*)&g_adst[d * 4];
    const float4 Kv = *(const float4*)g_K;
    lg[0] = as.x + ad.x + a * Kv.x;
    lg[1] = as.y + ad.y + a * Kv.y;
    lg[2] = as.z + ad.z + a * Kv.z;
    lg[3] = as.w + ad.w + a * Kv.w;
#pragma unroll
    for (int h = 0; h < 4; h++) lg[h] = lg[h] > 0.f ? lg[h] : 0.2f * lg[h];
}

// ---------------- K4: segment max ----------------
__global__ void logit_max_kernel(const void* __restrict__ ei, const float* __restrict__ ea) {
    long long e = (long long)blockIdx.x * blockDim.x + threadIdx.x;
    if (e >= ETOT) return;
    long long s, d;
    float lg[4];
    edge_logits(ei, ea, e, s, d, lg);
#pragma unroll
    for (int h = 0; h < 4; h++) atomicMaxF(&g_max[d * 4 + h], lg[h]);
}

// ---------------- K5: ex + denom ----------------
__global__ void softmax_kernel(const void* __restrict__ ei, const float* __restrict__ ea) {
    long long e = (long long)blockIdx.x * blockDim.x + threadIdx.x;
    if (e >= ETOT) return;
    long long s, d;
    float lg[4];
    edge_logits(ei, ea, e, s, d, lg);
    const float4 mv = *(const float4*)&g_max[d * 4];
    float e0 = __expf(lg[0] - mv.x);
    float e1 = __expf(lg[1] - mv.y);
    float e2 = __expf(lg[2] - mv.z);
    float e3 = __expf(lg[3] - mv.w);
    *(float4*)&g_ex[e * 4] = make_float4(e0, e1, e2, e3);
    float* dptr = &g_denom[d * 4];
    asm volatile("red.global.add.v4.f32 [%0], {%1,%2,%3,%4};"
                 :: "l"(dptr), "f"(e0), "f"(e1), "f"(e2), "f"(e3) : "memory");
}

// ---------------- K6: message scatter ----------------
__global__ void message_kernel(const void* __restrict__ ei) {
    long long idx = (long long)blockIdx.x * blockDim.x + threadIdx.x;
    long long e = idx >> 5;
    int lane = (int)(idx & 31);
    if (e >= ETOT) return;
    long long s, d;
    if (e < EE) {
        s = eidx(ei, e);
        d = eidx(ei, (long long)EE + e);
    } else {
        s = d = e - EE;
    }
    int h = lane >> 3;
    float ex = g_ex[e * 4 + h];
    float dn = g_denom[d * 4 + h];
    float al = ex / (dn + 1e-16f);
    float4 xv = ((const float4*)(g_xl + s * 128))[lane];
    float* dst = g_accum + d * 128 + lane * 4;
    asm volatile("red.global.add.v4.f32 [%0], {%1,%2,%3,%4};"
                 :: "l"(dst), "f"(xv.x * al), "f"(xv.y * al),
                    "f"(xv.z * al), "f"(xv.w * al) : "memory");
}

// ---------------- K7: bias + elu + fc + relu ----------------
__global__ void out_kernel(const float* __restrict__ gat_bias,
                           const float* __restrict__ fc_w,
                           const float* __restrict__ fc_b,
                           float* __restrict__ out) {
    long long idx = (long long)blockIdx.x * blockDim.x + threadIdx.x;
    int node = (int)(idx >> 5), lane = (int)(idx & 31);
    if (node >= NN) return;
    float a0 = 0.f, a1 = 0.f, a2 = 0.f, a3 = 0.f;
    const float4 av = *(const float4*)&g_accum[node * 128 + lane * 4];
    const float4 bv = *(const float4*)&gat_bias[lane * 4];
    float v[4] = {av.x + bv.x, av.y + bv.y, av.z + bv.z, av.w + bv.w};
#pragma unroll
    for (int r = 0; r < 4; r++) {
        float vv = v[r] > 0.f ? v[r] : expm1f(v[r]);
        int hc = lane * 4 + r;
        a0 += vv * fc_w[0 * 128 + hc];
        a1 += vv * fc_w[1 * 128 + hc];
        a2 += vv * fc_w[2 * 128 + hc];
        a3 += vv * fc_w[3 * 128 + hc];
    }
    for (int off = 16; off; off >>= 1) {
        a0 += __shfl_down_sync(0xffffffffu, a0, off);
        a1 += __shfl_down_sync(0xffffffffu, a1, off);
        a2 += __shfl_down_sync(0xffffffffu, a2, off);
        a3 += __shfl_down_sync(0xffffffffu, a3, off);
    }
    if (lane == 0) {
        out[node * 4 + 0] = fmaxf(a0 + fc_b[0], 0.f);
        out[node * 4 + 1] = fmaxf(a1 + fc_b[1], 0.f);
        out[node * 4 + 2] = fmaxf(a2 + fc_b[2], 0.f);
        out[node * 4 + 3] = fmaxf(a3 + fc_b[3], 0.f);
    }
}

// ---------------- launch ----------------
extern "C" void kernel_launch(void* const* d_in, const int* in_sizes, int n_in,
                              void* d_out, int out_size) {
    const float* x        = (const float*)d_in[0];
    const void*  ei       = d_in[1];
    const float* ea       = (const float*)d_in[2];
    const float* w_ih0    = (const float*)d_in[3];
    const float* w_hh0    = (const float*)d_in[4];
    const float* b_ih0    = (const float*)d_in[5];
    const float* b_hh0    = (const float*)d_in[6];
    const float* w_ih1    = (const float*)d_in[7];
    const float* w_hh1    = (const float*)d_in[8];
    const float* b_ih1    = (const float*)d_in[9];
    const float* b_hh1    = (const float*)d_in[10];
    const float* lin_w    = (const float*)d_in[11];
    const float* lin_ew   = (const float*)d_in[12];
    const float* att_src  = (const float*)d_in[13];
    const float* att_dst  = (const float*)d_in[14];
    const float* att_edge = (const float*)d_in[15];
    const float* gat_bias = (const float*)d_in[16];
    const float* fc_w     = (const float*)d_in[17];
    const float* fc_b     = (const float*)d_in[18];
    float* out = (float*)d_out;

    cudaFuncSetAttribute(lstm_mma_kernel, cudaFuncAttributeMaxDynamicSharedMemorySize,
                         LSTM_DSMEM);

    init_kernel<<<2048, 256>>>(lin_ew, att_edge);
    detect_kernel<<<1, 32>>>((const long long*)ei);
    mean_kernel<<<256, 256>>>(ea);
    lstm_mma_kernel<<<(NN + 127) / 128, 256, LSTM_DSMEM>>>(
        x, w_ih0, w_hh0, b_ih0, b_hh0, w_ih1, w_hh1, b_ih1, b_hh1);
    node_feat_kernel<<<(NN + 7) / 8, 256>>>(x, lin_w, att_src, att_dst);
    logit_max_kernel<<<(ETOT + 255) / 256, 256>>>(ei, ea);
    softmax_kernel<<<(ETOT + 255) / 256, 256>>>(ei, ea);
    message_kernel<<<(int)(((long long)ETOT * 32 + 255) / 256), 256>>>(ei);
    out_kernel<<<(NN * 32 + 255) / 256, 256>>>(gat_bias, fc_w, fc_b, out);
}

// round 6
// speedup vs baseline: 3.2704x; 1.1727x over previous
#include <cuda_runtime.h>
#include <cuda_fp16.h>
#include <stdint.h>

#define NN 50000
#define EE 800000
#define TT 24
#define ETOT (EE + NN)

// ---------------- scratch ----------------
__device__ float g_h2last[NN * 64];
__device__ float g_xl[NN * 128];
__device__ float g_asrc[NN * 4];
__device__ float g_adst[NN * 4];
__device__ float g_max[NN * 4];
__device__ float g_denom[NN * 4];
__device__ float g_accum[NN * 128];
__device__ float g_ex[(long long)ETOT * 4];
__device__ float g_meansum;
__device__ float g_K[4];
__device__ int   g_idx64;

// ---------------- helpers ----------------
__device__ __forceinline__ float tanh_hw(float x) {
    float y; asm("tanh.approx.f32 %0,%1;" : "=f"(y) : "f"(x)); return y;
}
__device__ __forceinline__ float sig_hw(float x) {
    return fmaf(tanh_hw(0.5f * x), 0.5f, 0.5f);
}
__device__ __forceinline__ long long eidx(const void* ei, long long pos) {
    if (g_idx64) return ((const long long*)ei)[pos];
    return (long long)((const int*)ei)[pos];
}
__device__ __forceinline__ void atomicMaxF(float* addr, float val) {
    if (val >= 0.f) atomicMax((int*)addr, __float_as_int(val));
    else            atomicMin((unsigned int*)addr, __float_as_uint(val));
}
__device__ __forceinline__ uint32_t smem_u32(const void* p) {
    uint32_t a;
    asm("{ .reg .u64 t; cvta.to.shared.u64 t, %1; cvt.u32.u64 %0, t; }"
        : "=r"(a) : "l"(p));
    return a;
}
__device__ __forceinline__ void ldsm4(uint32_t* r, uint32_t addr) {
    asm volatile("ldmatrix.sync.aligned.m8n8.x4.shared.b16 {%0,%1,%2,%3}, [%4];"
                 : "=r"(r[0]), "=r"(r[1]), "=r"(r[2]), "=r"(r[3]) : "r"(addr));
}
__device__ __forceinline__ void mma16816(float* d, const uint32_t* a, uint32_t b0, uint32_t b1) {
    asm volatile(
        "mma.sync.aligned.m16n8k16.row.col.f32.f16.f16.f32 "
        "{%0,%1,%2,%3}, {%4,%5,%6,%7}, {%8,%9}, {%0,%1,%2,%3};"
        : "+f"(d[0]), "+f"(d[1]), "+f"(d[2]), "+f"(d[3])
        : "r"(a[0]), "r"(a[1]), "r"(a[2]), "r"(a[3]), "r"(b0), "r"(b1));
}
__device__ __forceinline__ void packpair16(float a, float b, uint32_t& hi, uint32_t& lo) {
    __half2 p = __floats2half2_rn(a, b);
    hi = *(uint32_t*)&p;
    float ra = a - __low2float(p), rb = b - __high2float(p);
    __half2 q = __floats2half2_rn(ra, rb);
    lo = *(uint32_t*)&q;
}

// ---------------- SMEM layout (bytes, from 1024-aligned base) ----------------
#define OFF_WC  0          // Wcat fp16 [256 rows][128 k], 256B/row, 64KB
#define OFF_W0  65536      // W0   fp16 [256 rows][64 k], 128B/row, 32KB
#define OFF_HHI 98304      // h hi fp16 [128 rows][256B] chunks 0-7:h0, 8-15:h1
#define OFF_HLO 131072     // h lo
#define OFF_XS  163840     // float[24*128] = 12KB
#define OFF_WB  176128     // float[768]: w_ih0 | b0 | b1
#define LSTM_DSMEM (179200 + 1024)

__device__ __forceinline__ uint32_t h_off(int row, int chunk, int tg) {
    return (uint32_t)(row * 256 + ((chunk ^ (row & 7)) << 4) + (tg << 2));
}
// A fragment (m16 x k16) address: group g, m-tile mt, k-tile kt
__device__ __forceinline__ uint32_t a_off(int g, int mt, int kt, int lane) {
    int tl = lane >> 3, lr = lane & 7;
    int row = g * 64 + mt * 16 + ((tl & 1) << 3) + lr;
    int chunk = 2 * kt + (tl >> 1);
    return (uint32_t)(row * 256 + ((chunk ^ (row & 7)) << 4));
}
// B fragment (dual n8 tiles x k16) for Wcat: rows gt*64 + jj + nt*8
__device__ __forceinline__ uint32_t bc_off(int gt, int jj, int kt, int lane) {
    int tl = lane >> 3, lr = lane & 7;
    int nt = tl & 1, cq = tl >> 1;
    int row = gt * 64 + jj + nt * 8 + lr;
    int chunk = 2 * kt + cq;
    return (uint32_t)(row * 256 + ((chunk ^ (row & 7)) << 4));
}
// B fragment for W0 (row stride 128B, chunks 0..7)
__device__ __forceinline__ uint32_t b0_off(int gt, int jj, int kt, int lane) {
    int tl = lane >> 3, lr = lane & 7;
    int nt = tl & 1, cq = tl >> 1;
    int row = gt * 64 + jj + nt * 8 + lr;
    int chunk = 2 * kt + cq;
    return (uint32_t)(row * 128 + ((chunk ^ (row & 7)) << 4));
}

// ---------------- K0: init ----------------
__global__ void init_kernel(const float* __restrict__ lin_edge_w,
                            const float* __restrict__ att_edge) {
    long long stride = (long long)gridDim.x * blockDim.x;
    long long i0 = (long long)blockIdx.x * blockDim.x + threadIdx.x;
    for (long long i = i0; i < (long long)NN * 128; i += stride) g_accum[i] = 0.f;
    for (long long i = i0; i < (long long)NN * 4; i += stride) {
        g_denom[i] = 0.f;
        ((int*)g_max)[i] = 0xFF800000;
    }
    if (i0 == 0) g_meansum = 0.f;
    if (i0 < 4) {
        float s = 0.f;
        for (int c = 0; c < 32; c++) s += lin_edge_w[i0 * 32 + c] * att_edge[i0 * 32 + c];
        g_K[i0] = s;
    }
}

__global__ void detect_kernel(const long long* __restrict__ ei) {
    if (blockIdx.x == 0 && threadIdx.x == 0) {
        int ok = 1;
        for (int i = 0; i < 512; i++) {
            long long v = ei[i];
            if (v < 0 || v >= NN) { ok = 0; break; }
        }
        g_idx64 = ok;
    }
}

__global__ void mean_kernel(const float* __restrict__ ea) {
    __shared__ float red[256];
    float s = 0.f;
    for (long long i = (long long)blockIdx.x * blockDim.x + threadIdx.x; i < EE;
         i += (long long)gridDim.x * blockDim.x)
        s += ea[i];
    red[threadIdx.x] = s;
    __syncthreads();
    for (int o = 128; o; o >>= 1) {
        if (threadIdx.x < o) red[threadIdx.x] += red[threadIdx.x + o];
        __syncthreads();
    }
    if (threadIdx.x == 0) atomicAdd(&g_meansum, red[0]);
}

// ---------------- K2: HMMA LSTM, 2 independent 64-node groups ----------------
// fp16, 2-product A-split (A exact to ~2^-22, W rounded once to 2^-12).
__global__ void __launch_bounds__(256, 1) lstm_mma_kernel(
    const float* __restrict__ x,
    const float* __restrict__ w_ih0, const float* __restrict__ w_hh0,
    const float* __restrict__ b_ih0, const float* __restrict__ b_hh0,
    const float* __restrict__ w_ih1, const float* __restrict__ w_hh1,
    const float* __restrict__ b_ih1, const float* __restrict__ b_hh1)
{
    extern __shared__ char dsm_raw[];
    char* dsm = (char*)(((unsigned long long)dsm_raw + 1023ULL) & ~1023ULL);
    const uint32_t smb = smem_u32(dsm);

    const int tid = threadIdx.x;
    const int w = tid >> 5, lane = tid & 31;
    const int g = w >> 2, wg = w & 3;
    const int tg = lane & 3, gg = lane >> 2;
    const int jj = wg * 16;
    const int nodeBase = blockIdx.x * 128;

    float* xs  = (float*)(dsm + OFF_XS);
    float* wbp = (float*)(dsm + OFF_WB);

    // Wcat = [w_ih1 | w_hh1] fp16, swizzled
    for (int i = tid; i < 256 * 128; i += 256) {
        int n = i >> 7, k = i & 127;
        float v = (k < 64) ? w_ih1[n * 64 + k] : w_hh1[n * 64 + (k - 64)];
        uint32_t off = (uint32_t)(n * 256 + (((k >> 3) ^ (n & 7)) << 4) + ((k & 7) << 1));
        *(__half*)(dsm + OFF_WC + off) = __float2half_rn(v);
    }
    // W0 = w_hh0 fp16, swizzled (row stride 128B)
    for (int i = tid; i < 256 * 64; i += 256) {
        int n = i >> 6, k = i & 63;
        uint32_t off = (uint32_t)(n * 128 + (((k >> 3) ^ (n & 7)) << 4) + ((k & 7) << 1));
        *(__half*)(dsm + OFF_W0 + off) = __float2half_rn(w_hh0[n * 64 + k]);
    }
    // x slice + fused consts
    for (int i = tid; i < TT * 128; i += 256) {
        int t = i >> 7, nl = i & 127;
        int nd = nodeBase + nl;
        xs[i] = (nd < NN) ? x[nd * 32 + 8 + t] : 0.f;
    }
    if (tid < 256) {
        wbp[tid]       = w_ih0[tid];
        wbp[256 + tid] = b_ih0[tid] + b_hh0[tid];
        wbp[512 + tid] = b_ih1[tid] + b_hh1[tid];
    }
    // zero h arrays: HHI+HLO are contiguous 64KB = 16384 words total
    for (int i = tid; i < 16384; i += 256)
        ((uint32_t*)(dsm + OFF_HHI))[i] = 0u;
    __syncthreads();

    // per-thread consts: [gt*4 + nt*2 + e]
    float cwx[16], cb0[16], cb1[16];
#pragma unroll
    for (int gt = 0; gt < 4; gt++)
#pragma unroll
        for (int nt = 0; nt < 2; nt++)
#pragma unroll
            for (int e = 0; e < 2; e++) {
                int ci = gt * 4 + nt * 2 + e;
                int jg = gt * 64 + jj + nt * 8 + tg * 2 + e;
                cwx[ci] = wbp[jg];
                cb0[ci] = wbp[256 + jg];
                cb1[ci] = wbp[512 + jg];
            }

    float c0[32], c1[32];
#pragma unroll
    for (int i = 0; i < 32; i++) { c0[i] = 0.f; c1[i] = 0.f; }
    uint32_t stash[32];
    const int barid = 1 + g;

#pragma unroll 1
    for (int t = 0; t < TT; t++) {
        // ============ layer 0 (K=64, B=W0) ============
#pragma unroll
        for (int mt = 0; mt < 4; mt++) {
            float acc[32];
#pragma unroll
            for (int i = 0; i < 32; i++) acc[i] = 0.f;
#pragma unroll
            for (int kt = 0; kt < 4; kt++) {
                uint32_t Ah[4], Al[4];
                ldsm4(Ah, smb + OFF_HHI + a_off(g, mt, kt, lane));
                ldsm4(Al, smb + OFF_HLO + a_off(g, mt, kt, lane));
#pragma unroll
                for (int gt = 0; gt < 4; gt++) {
                    uint32_t B[4];
                    ldsm4(B, smb + OFF_W0 + b0_off(gt, jj, kt, lane));
                    mma16816(acc + gt * 8,     Ah, B[0], B[2]);
                    mma16816(acc + gt * 8,     Al, B[0], B[2]);
                    mma16816(acc + gt * 8 + 4, Ah, B[1], B[3]);
                    mma16816(acc + gt * 8 + 4, Al, B[1], B[3]);
                }
            }
            int r0 = g * 64 + mt * 16 + gg;
            float x0 = xs[t * 128 + r0], x1 = xs[t * 128 + r0 + 8];
            float hv[8];
#pragma unroll
            for (int nt = 0; nt < 2; nt++)
#pragma unroll
                for (int q = 0; q < 4; q++) {
                    int e = q & 1, cbi = nt * 2 + e;
                    float xv = (q >> 1) ? x1 : x0;
                    float gi = acc[nt * 4 + q]      + fmaf(xv, cwx[cbi],      cb0[cbi]);
                    float gf = acc[8 + nt * 4 + q]  + fmaf(xv, cwx[4 + cbi],  cb0[4 + cbi]);
                    float gG = acc[16 + nt * 4 + q] + fmaf(xv, cwx[8 + cbi],  cb0[8 + cbi]);
                    float go = acc[24 + nt * 4 + q] + fmaf(xv, cwx[12 + cbi], cb0[12 + cbi]);
                    float c = sig_hw(gf) * c0[mt * 8 + nt * 4 + q] + sig_hw(gi) * tanh_hw(gG);
                    c0[mt * 8 + nt * 4 + q] = c;
                    hv[nt * 4 + q] = sig_hw(go) * tanh_hw(c);
                }
#pragma unroll
            for (int nt = 0; nt < 2; nt++) {
                packpair16(hv[nt * 4 + 0], hv[nt * 4 + 1],
                           stash[mt * 8 + nt * 4 + 0], stash[mt * 8 + nt * 4 + 1]);
                packpair16(hv[nt * 4 + 2], hv[nt * 4 + 3],
                           stash[mt * 8 + nt * 4 + 2], stash[mt * 8 + nt * 4 + 3]);
            }
        }
        asm volatile("bar.sync %0, 128;" :: "r"(barid) : "memory");
#pragma unroll
        for (int mt = 0; mt < 4; mt++)
#pragma unroll
            for (int nt = 0; nt < 2; nt++) {
                int row = g * 64 + mt * 16 + gg;
                int ch = 2 * wg + nt;
                uint32_t o1 = h_off(row, ch, tg), o2 = h_off(row + 8, ch, tg);
                *(uint32_t*)(dsm + OFF_HHI + o1) = stash[mt * 8 + nt * 4 + 0];
                *(uint32_t*)(dsm + OFF_HLO + o1) = stash[mt * 8 + nt * 4 + 1];
                *(uint32_t*)(dsm + OFF_HHI + o2) = stash[mt * 8 + nt * 4 + 2];
                *(uint32_t*)(dsm + OFF_HLO + o2) = stash[mt * 8 + nt * 4 + 3];
            }
        asm volatile("bar.sync %0, 128;" :: "r"(barid) : "memory");

        // ============ layer 1 (K=128: h0|h1, B=Wcat) ============
#pragma unroll
        for (int mt = 0; mt < 4; mt++) {
            float acc[32];
#pragma unroll
            for (int i = 0; i < 32; i++) acc[i] = 0.f;
#pragma unroll
            for (int kt = 0; kt < 8; kt++) {
                uint32_t Ah[4], Al[4];
                ldsm4(Ah, smb + OFF_HHI + a_off(g, mt, kt, lane));
                ldsm4(Al, smb + OFF_HLO + a_off(g, mt, kt, lane));
#pragma unroll
                for (int gt = 0; gt < 4; gt++) {
                    uint32_t B[4];
                    ldsm4(B, smb + OFF_WC + bc_off(gt, jj, kt, lane));
                    mma16816(acc + gt * 8,     Ah, B[0], B[2]);
                    mma16816(acc + gt * 8,     Al, B[0], B[2]);
                    mma16816(acc + gt * 8 + 4, Ah, B[1], B[3]);
                    mma16816(acc + gt * 8 + 4, Al, B[1], B[3]);
                }
            }
            int r0 = g * 64 + mt * 16 + gg;
            float hv[8];
#pragma unroll
            for (int nt = 0; nt < 2; nt++)
#pragma unroll
                for (int q = 0; q < 4; q++) {
                    int e = q & 1, cbi = nt * 2 + e;
                    float gi = acc[nt * 4 + q]      + cb1[cbi];
                    float gf = acc[8 + nt * 4 + q]  + cb1[4 + cbi];
                    float gG = acc[16 + nt * 4 + q] + cb1[8 + cbi];
                    float go = acc[24 + nt * 4 + q] + cb1[12 + cbi];
                    float c = sig_hw(gf) * c1[mt * 8 + nt * 4 + q] + sig_hw(gi) * tanh_hw(gG);
                    c1[mt * 8 + nt * 4 + q] = c;
                    hv[nt * 4 + q] = sig_hw(go) * tanh_hw(c);
                }
            if (t == TT - 1) {
                int nd0 = nodeBase + r0, nd1 = nd0 + 8;
#pragma unroll
                for (int nt = 0; nt < 2; nt++) {
                    int j0 = jj + nt * 8 + tg * 2;
                    if (nd0 < NN)
                        *(float2*)&g_h2last[nd0 * 64 + j0] = make_float2(hv[nt * 4 + 0], hv[nt * 4 + 1]);
                    if (nd1 < NN)
                        *(float2*)&g_h2last[nd1 * 64 + j0] = make_float2(hv[nt * 4 + 2], hv[nt * 4 + 3]);
                }
            } else {
#pragma unroll
                for (int nt = 0; nt < 2; nt++) {
                    packpair16(hv[nt * 4 + 0], hv[nt * 4 + 1],
                               stash[mt * 8 + nt * 4 + 0], stash[mt * 8 + nt * 4 + 1]);
                    packpair16(hv[nt * 4 + 2], hv[nt * 4 + 3],
                               stash[mt * 8 + nt * 4 + 2], stash[mt * 8 + nt * 4 + 3]);
                }
            }
        }
        if (t < TT - 1) {
            asm volatile("bar.sync %0, 128;" :: "r"(barid) : "memory");
#pragma unroll
            for (int mt = 0; mt < 4; mt++)
#pragma unroll
                for (int nt = 0; nt < 2; nt++) {
                    int row = g * 64 + mt * 16 + gg;
                    int ch = 8 + 2 * wg + nt;
                    uint32_t o1 = h_off(row, ch, tg), o2 = h_off(row + 8, ch, tg);
                    *(uint32_t*)(dsm + OFF_HHI + o1) = stash[mt * 8 + nt * 4 + 0];
                    *(uint32_t*)(dsm + OFF_HLO + o1) = stash[mt * 8 + nt * 4 + 1];
                    *(uint32_t*)(dsm + OFF_HHI + o2) = stash[mt * 8 + nt * 4 + 2];
                    *(uint32_t*)(dsm + OFF_HLO + o2) = stash[mt * 8 + nt * 4 + 3];
                }
            asm volatile("bar.sync %0, 128;" :: "r"(barid) : "memory");
        }
    }
}

// ---------------- K3: xl = combined @ lin_w^T ; a_src, a_dst ----------------
__global__ void node_feat_kernel(const float* __restrict__ x,
                                 const float* __restrict__ lin_w,
                                 const float* __restrict__ att_src,
                                 const float* __restrict__ att_dst) {
    __shared__ float sW[72 * 128];
    __shared__ float scomb[8][72];
    __shared__ float ssrc[128], sdst[128];
    int tid = threadIdx.x;
    for (int i = tid; i < 72 * 128; i += 256) {
        int d = i >> 7, g = i & 127;
        sW[i] = lin_w[g * 72 + d];
    }
    if (tid < 128) { ssrc[tid] = att_src[tid]; sdst[tid] = att_dst[tid]; }
    int nl = tid >> 5, lane = tid & 31;
    int node = blockIdx.x * 8 + nl;
    for (int d = lane; d < 72; d += 32)
        scomb[nl][d] = (node < NN) ? (d < 64 ? g_h2last[node * 64 + d]
                                             : x[node * 32 + (d - 64)])
                                   : 0.f;
    __syncthreads();
    float o0 = 0.f, o1 = 0.f, o2 = 0.f, o3 = 0.f;
    for (int d = 0; d < 72; d++) {
        float cv = scomb[nl][d];
        const float4 w4 = *(const float4*)&sW[d * 128 + lane * 4];
        o0 += cv * w4.x; o1 += cv * w4.y; o2 += cv * w4.z; o3 += cv * w4.w;
    }
    float ps = o0 * ssrc[lane * 4] + o1 * ssrc[lane * 4 + 1] +
               o2 * ssrc[lane * 4 + 2] + o3 * ssrc[lane * 4 + 3];
    float pd = o0 * sdst[lane * 4] + o1 * sdst[lane * 4 + 1] +
               o2 * sdst[lane * 4 + 2] + o3 * sdst[lane * 4 + 3];
    for (int off = 4; off; off >>= 1) {
        ps += __shfl_down_sync(0xffffffffu, ps, off, 8);
        pd += __shfl_down_sync(0xffffffffu, pd, off, 8);
    }
    if (node < NN) {
        *(float4*)&g_xl[node * 128 + lane * 4] = make_float4(o0, o1, o2, o3);
        if ((lane & 7) == 0) {
            int h = lane >> 3;
            g_asrc[node * 4 + h] = ps;
            g_adst[node * 4 + h] = pd;
        }
    }
}

// ---------------- per-edge logit ----------------
__device__ __forceinline__ void edge_logits(const void* ei, const float* ea,
                                            long long e, long long& s, long long& d,
                                            float lg[4]) {
    float a;
    if (e < EE) {
        s = eidx(ei, e);
        d = eidx(ei, (long long)EE + e);
        a = ea[e];
    } else {
        s = d = e - EE;
        a = g_meansum * (1.f / EE);
    }
    const float4 as = *(const float4*)&g_asrc[s * 4];
    const float4 ad = *(const float4*)&g_adst[d * 4];
    const float4 Kv = *(const float4*)g_K;
    lg[0] = as.x + ad.x + a * Kv.x;
    lg[1] = as.y + ad.y + a * Kv.y;
    lg[2] = as.z + ad.z + a * Kv.z;
    lg[3] = as.w + ad.w + a * Kv.w;
#pragma unroll
    for (int h = 0; h < 4; h++) lg[h] = lg[h] > 0.f ? lg[h] : 0.2f * lg[h];
}

// ---------------- K4: segment max (also caches logits into g_ex) ----------------
__global__ void logit_max_kernel(const void* __restrict__ ei, const float* __restrict__ ea) {
    long long e = (long long)blockIdx.x * blockDim.x + threadIdx.x;
    if (e >= ETOT) return;
    long long s, d;
    float lg[4];
    edge_logits(ei, ea, e, s, d, lg);
    *(float4*)&g_ex[e * 4] = make_float4(lg[0], lg[1], lg[2], lg[3]);
#pragma unroll
    for (int h = 0; h < 4; h++) atomicMaxF(&g_max[d * 4 + h], lg[h]);
}

// ---------------- K5: ex + denom (reads cached logits) ----------------
__global__ void softmax_kernel(const void* __restrict__ ei) {
    long long e = (long long)blockIdx.x * blockDim.x + threadIdx.x;
    if (e >= ETOT) return;
    long long d = (e < EE) ? eidx(ei, (long long)EE + e) : (e - EE);
    const float4 lg = *(const float4*)&g_ex[e * 4];
    const float4 mv = *(const float4*)&g_max[d * 4];
    float e0 = __expf(lg.x - mv.x);
    float e1 = __expf(lg.y - mv.y);
    float e2 = __expf(lg.z - mv.z);
    float e3 = __expf(lg.w - mv.w);
    *(float4*)&g_ex[e * 4] = make_float4(e0, e1, e2, e3);
    float* dptr = &g_denom[d * 4];
    asm volatile("red.global.add.v4.f32 [%0], {%1,%2,%3,%4};"
                 :: "l"(dptr), "f"(e0), "f"(e1), "f"(e2), "f"(e3) : "memory");
}

// ---------------- K6: message scatter ----------------
__global__ void message_kernel(const void* __restrict__ ei) {
    long long idx = (long long)blockIdx.x * blockDim.x + threadIdx.x;
    long long e = idx >> 5;
    int lane = (int)(idx & 31);
    if (e >= ETOT) return;
    long long s, d;
    if (e < EE) {
        s = eidx(ei, e);
        d = eidx(ei, (long long)EE + e);
    } else {
        s = d = e - EE;
    }
    int h = lane >> 3;
    float ex = g_ex[e * 4 + h];
    float dn = g_denom[d * 4 + h];
    float al = ex / (dn + 1e-16f);
    float4 xv = ((const float4*)(g_xl + s * 128))[lane];
    float* dst = g_accum + d * 128 + lane * 4;
    asm volatile("red.global.add.v4.f32 [%0], {%1,%2,%3,%4};"
                 :: "l"(dst), "f"(xv.x * al), "f"(xv.y * al),
                    "f"(xv.z * al), "f"(xv.w * al) : "memory");
}

// ---------------- K7: bias + elu + fc + relu ----------------
__global__ void out_kernel(const float* __restrict__ gat_bias,
                           const float* __restrict__ fc_w,
                           const float* __restrict__ fc_b,
                           float* __restrict__ out) {
    long long idx = (long long)blockIdx.x * blockDim.x + threadIdx.x;
    int node = (int)(idx >> 5), lane = (int)(idx & 31);
    if (node >= NN) return;
    float a0 = 0.f, a1 = 0.f, a2 = 0.f, a3 = 0.f;
    const float4 av = *(const float4*)&g_accum[node * 128 + lane * 4];
    const float4 bv = *(const float4*)&gat_bias[lane * 4];
    float v[4] = {av.x + bv.x, av.y + bv.y, av.z + bv.z, av.w + bv.w};
#pragma unroll
    for (int r = 0; r < 4; r++) {
        float vv = v[r] > 0.f ? v[r] : expm1f(v[r]);
        int hc = lane * 4 + r;
        a0 += vv * fc_w[0 * 128 + hc];
        a1 += vv * fc_w[1 * 128 + hc];
        a2 += vv * fc_w[2 * 128 + hc];
        a3 += vv * fc_w[3 * 128 + hc];
    }
    for (int off = 16; off; off >>= 1) {
        a0 += __shfl_down_sync(0xffffffffu, a0, off);
        a1 += __shfl_down_sync(0xffffffffu, a1, off);
        a2 += __shfl_down_sync(0xffffffffu, a2, off);
        a3 += __shfl_down_sync(0xffffffffu, a3, off);
    }
    if (lane == 0) {
        out[node * 4 + 0] = fmaxf(a0 + fc_b[0], 0.f);
        out[node * 4 + 1] = fmaxf(a1 + fc_b[1], 0.f);
        out[node * 4 + 2] = fmaxf(a2 + fc_b[2], 0.f);
        out[node * 4 + 3] = fmaxf(a3 + fc_b[3], 0.f);
    }
}

// ---------------- launch ----------------
extern "C" void kernel_launch(void* const* d_in, const int* in_sizes, int n_in,
                              void* d_out, int out_size) {
    const float* x        = (const float*)d_in[0];
    const void*  ei       = d_in[1];
    const float* ea       = (const float*)d_in[2];
    const float* w_ih0    = (const float*)d_in[3];
    const float* w_hh0    = (const float*)d_in[4];
    const float* b_ih0    = (const float*)d_in[5];
    const float* b_hh0    = (const float*)d_in[6];
    const float* w_ih1    = (const float*)d_in[7];
    const float* w_hh1    = (const float*)d_in[8];
    const float* b_ih1    = (const float*)d_in[9];
    const float* b_hh1    = (const float*)d_in[10];
    const float* lin_w    = (const float*)d_in[11];
    const float* lin_ew   = (const float*)d_in[12];
    const float* att_src  = (const float*)d_in[13];
    const float* att_dst  = (const float*)d_in[14];
    const float* att_edge = (const float*)d_in[15];
    const float* gat_bias = (const float*)d_in[16];
    const float* fc_w     = (const float*)d_in[17];
    const float* fc_b     = (const float*)d_in[18];
    float* out = (float*)d_out;

    cudaFuncSetAttribute(lstm_mma_kernel, cudaFuncAttributeMaxDynamicSharedMemorySize,
                         LSTM_DSMEM);

    init_kernel<<<2048, 256>>>(lin_ew, att_edge);
    detect_kernel<<<1, 32>>>((const long long*)ei);
    mean_kernel<<<256, 256>>>(ea);
    lstm_mma_kernel<<<(NN + 127) / 128, 256, LSTM_DSMEM>>>(
        x, w_ih0, w_hh0, b_ih0, b_hh0, w_ih1, w_hh1, b_ih1, b_hh1);
    node_feat_kernel<<<(NN + 7) / 8, 256>>>(x, lin_w, att_src, att_dst);
    logit_max_kernel<<<(ETOT + 255) / 256, 256>>>(ei, ea);
    softmax_kernel<<<(ETOT + 255) / 256, 256>>>(ei);
    message_kernel<<<(int)(((long long)ETOT * 32 + 255) / 256), 256>>>(ei);
    out_kernel<<<(NN * 32 + 255) / 256, 256>>>(gat_bias, fc_w, fc_b, out);
}

// round 7
// speedup vs baseline: 4.5040x; 1.3772x over previous
#include <cuda_runtime.h>
#include <cuda_fp16.h>
#include <stdint.h>

#define NN 50000
#define EE 800000
#define TT 24
#define ETOT (EE + NN)

// ---------------- scratch ----------------
__device__ float g_h2last[NN * 64];
__device__ float g_xl[NN * 128];
__device__ float g_asrc[NN * 4];
__device__ float g_adst[NN * 4];
__device__ float g_max[NN * 4];
__device__ float g_denom[NN * 4];
__device__ float g_accum[NN * 128];
__device__ float g_ex[(long long)ETOT * 4];
__device__ float g_meansum;
__device__ float g_K[4];
__device__ int   g_idx64;

// ---------------- helpers ----------------
__device__ __forceinline__ float tanh_hw(float x) {
    float y; asm("tanh.approx.f32 %0,%1;" : "=f"(y) : "f"(x)); return y;
}
__device__ __forceinline__ float sig_hw(float x) {
    return fmaf(tanh_hw(0.5f * x), 0.5f, 0.5f);
}
__device__ __forceinline__ long long eidx(const void* ei, long long pos) {
    if (g_idx64) return ((const long long*)ei)[pos];
    return (long long)((const int*)ei)[pos];
}
__device__ __forceinline__ void atomicMaxF(float* addr, float val) {
    if (val >= 0.f) atomicMax((int*)addr, __float_as_int(val));
    else            atomicMin((unsigned int*)addr, __float_as_uint(val));
}
__device__ __forceinline__ uint32_t smem_u32(const void* p) {
    uint32_t a;
    asm("{ .reg .u64 t; cvta.to.shared.u64 t, %1; cvt.u32.u64 %0, t; }"
        : "=r"(a) : "l"(p));
    return a;
}
__device__ __forceinline__ void ldsm4(uint32_t* r, uint32_t addr) {
    asm volatile("ldmatrix.sync.aligned.m8n8.x4.shared.b16 {%0,%1,%2,%3}, [%4];"
                 : "=r"(r[0]), "=r"(r[1]), "=r"(r[2]), "=r"(r[3]) : "r"(addr));
}
__device__ __forceinline__ void mma16816(float* d, const uint32_t* a, uint32_t b0, uint32_t b1) {
    asm volatile(
        "mma.sync.aligned.m16n8k16.row.col.f32.f16.f16.f32 "
        "{%0,%1,%2,%3}, {%4,%5,%6,%7}, {%8,%9}, {%0,%1,%2,%3};"
        : "+f"(d[0]), "+f"(d[1]), "+f"(d[2]), "+f"(d[3])
        : "r"(a[0]), "r"(a[1]), "r"(a[2]), "r"(a[3]), "r"(b0), "r"(b1));
}

// ---------------- SMEM layout (bytes, from 1024-aligned base) ----------------
#define OFF_WC  0          // Wcat fp16 [256 rows][128 k], 256B/row, 64KB
#define OFF_W0  65536      // W0   fp16 [256 rows][64 k], 128B/row, 32KB (used once)
#define OFF_H   98304      // h fp16 [128 rows][256B]: chunks 0-7 h0, 8-15 h1, 32KB
#define OFF_XS  131072     // float[24*128] = 12KB
#define OFF_WB  143360     // float[768]: w_ih0 | b0 | b1
#define LSTM_DSMEM (146432 + 1024)

__device__ __forceinline__ uint32_t h_off(int row, int chunk, int tg) {
    return (uint32_t)(row * 256 + ((chunk ^ (row & 7)) << 4) + (tg << 2));
}
__device__ __forceinline__ uint32_t a_off(int g, int mt, int kt, int lane) {
    int tl = lane >> 3, lr = lane & 7;
    int row = g * 64 + mt * 16 + ((tl & 1) << 3) + lr;
    int chunk = 2 * kt + (tl >> 1);
    return (uint32_t)(row * 256 + ((chunk ^ (row & 7)) << 4));
}
__device__ __forceinline__ uint32_t bc_off(int gt, int jj, int kt, int lane) {
    int tl = lane >> 3, lr = lane & 7;
    int nt = tl & 1, cq = tl >> 1;
    int row = gt * 64 + jj + nt * 8 + lr;
    int chunk = 2 * kt + cq;
    return (uint32_t)(row * 256 + ((chunk ^ (row & 7)) << 4));
}
__device__ __forceinline__ uint32_t b0_off(int gt, int jj, int kt, int lane) {
    int tl = lane >> 3, lr = lane & 7;
    int nt = tl & 1, cq = tl >> 1;
    int row = gt * 64 + jj + nt * 8 + lr;
    int chunk = 2 * kt + cq;
    return (uint32_t)(row * 128 + ((chunk ^ (row & 7)) << 4));
}

// ---------------- K0: init ----------------
__global__ void init_kernel(const float* __restrict__ lin_edge_w,
                            const float* __restrict__ att_edge) {
    long long stride = (long long)gridDim.x * blockDim.x;
    long long i0 = (long long)blockIdx.x * blockDim.x + threadIdx.x;
    for (long long i = i0; i < (long long)NN * 128; i += stride) g_accum[i] = 0.f;
    for (long long i = i0; i < (long long)NN * 4; i += stride) {
        g_denom[i] = 0.f;
        ((int*)g_max)[i] = 0xFF800000;
    }
    if (i0 == 0) g_meansum = 0.f;
    if (i0 < 4) {
        float s = 0.f;
        for (int c = 0; c < 32; c++) s += lin_edge_w[i0 * 32 + c] * att_edge[i0 * 32 + c];
        g_K[i0] = s;
    }
}

__global__ void detect_kernel(const long long* __restrict__ ei) {
    if (blockIdx.x == 0 && threadIdx.x == 0) {
        int ok = 1;
        for (int i = 0; i < 512; i++) {
            long long v = ei[i];
            if (v < 0 || v >= NN) { ok = 0; break; }
        }
        g_idx64 = ok;
    }
}

__global__ void mean_kernel(const float* __restrict__ ea) {
    __shared__ float red[256];
    float s = 0.f;
    for (long long i = (long long)blockIdx.x * blockDim.x + threadIdx.x; i < EE;
         i += (long long)gridDim.x * blockDim.x)
        s += ea[i];
    red[threadIdx.x] = s;
    __syncthreads();
    for (int o = 128; o; o >>= 1) {
        if (threadIdx.x < o) red[threadIdx.x] += red[threadIdx.x + o];
        __syncthreads();
    }
    if (threadIdx.x == 0) atomicAdd(&g_meansum, red[0]);
}

// ---------------- K2: HMMA LSTM ----------------
// 2 independent 64-node groups, single fp16 product, W0 in registers,
// group-1 skew to de-phase MUFU vs tensor phases.
__global__ void __launch_bounds__(256, 1) lstm_mma_kernel(
    const float* __restrict__ x,
    const float* __restrict__ w_ih0, const float* __restrict__ w_hh0,
    const float* __restrict__ b_ih0, const float* __restrict__ b_hh0,
    const float* __restrict__ w_ih1, const float* __restrict__ w_hh1,
    const float* __restrict__ b_ih1, const float* __restrict__ b_hh1)
{
    extern __shared__ char dsm_raw[];
    char* dsm = (char*)(((unsigned long long)dsm_raw + 1023ULL) & ~1023ULL);
    const uint32_t smb = smem_u32(dsm);

    const int tid = threadIdx.x;
    const int w = tid >> 5, lane = tid & 31;
    const int g = w >> 2, wg = w & 3;
    const int tg = lane & 3, gg = lane >> 2;
    const int jj = wg * 16;
    const int nodeBase = blockIdx.x * 128;

    float* xs  = (float*)(dsm + OFF_XS);
    float* wbp = (float*)(dsm + OFF_WB);

    // Wcat = [w_ih1 | w_hh1] fp16, swizzled
    for (int i = tid; i < 256 * 128; i += 256) {
        int n = i >> 7, k = i & 127;
        float v = (k < 64) ? w_ih1[n * 64 + k] : w_hh1[n * 64 + (k - 64)];
        uint32_t off = (uint32_t)(n * 256 + (((k >> 3) ^ (n & 7)) << 4) + ((k & 7) << 1));
        *(__half*)(dsm + OFF_WC + off) = __float2half_rn(v);
    }
    // W0 staged fp16, swizzled (row stride 128B)
    for (int i = tid; i < 256 * 64; i += 256) {
        int n = i >> 6, k = i & 63;
        uint32_t off = (uint32_t)(n * 128 + (((k >> 3) ^ (n & 7)) << 4) + ((k & 7) << 1));
        *(__half*)(dsm + OFF_W0 + off) = __float2half_rn(w_hh0[n * 64 + k]);
    }
    // x slice + fused consts
    for (int i = tid; i < TT * 128; i += 256) {
        int t = i >> 7, nl = i & 127;
        int nd = nodeBase + nl;
        xs[i] = (nd < NN) ? x[nd * 32 + 8 + t] : 0.f;
    }
    if (tid < 256) {
        wbp[tid]       = w_ih0[tid];
        wbp[256 + tid] = b_ih0[tid] + b_hh0[tid];
        wbp[512 + tid] = b_ih1[tid] + b_hh1[tid];
    }
    // zero h array: 32KB = 8192 words
    for (int i = tid; i < 8192; i += 256)
        ((uint32_t*)(dsm + OFF_H))[i] = 0u;
    __syncthreads();

    // W0 fragments -> registers (one-time)
    uint32_t w0r[4][4][4];
#pragma unroll
    for (int gt = 0; gt < 4; gt++)
#pragma unroll
        for (int kt = 0; kt < 4; kt++)
            ldsm4(w0r[gt][kt], smb + OFF_W0 + b0_off(gt, jj, kt, lane));

    float c0[32], c1[32];
#pragma unroll
    for (int i = 0; i < 32; i++) { c0[i] = 0.f; c1[i] = 0.f; }
    uint32_t stash[16];
    const int barid = 1 + g;

    // one-time skew for group 1: persists (groups never cross-sync)
    if (g == 1) {
        float z = (float)tid * 1e-30f;
#pragma unroll 1
        for (int i = 0; i < 600; i++)
            asm volatile("fma.rn.f32 %0, %0, 0f3F800001, 0f00000000;" : "+f"(z));
        if (z > 1e30f) wbp[760] = z;  // never taken; defeats DCE
    }

#pragma unroll 1
    for (int t = 0; t < TT; t++) {
        // ============ layer 0 (K=64, B=W0 in regs) ============
#pragma unroll
        for (int mt = 0; mt < 4; mt++) {
            float acc[32];
#pragma unroll
            for (int i = 0; i < 32; i++) acc[i] = 0.f;
#pragma unroll
            for (int kt = 0; kt < 4; kt++) {
                uint32_t Ah[4];
                ldsm4(Ah, smb + OFF_H + a_off(g, mt, kt, lane));
#pragma unroll
                for (int gt = 0; gt < 4; gt++) {
                    mma16816(acc + gt * 8,     Ah, w0r[gt][kt][0], w0r[gt][kt][2]);
                    mma16816(acc + gt * 8 + 4, Ah, w0r[gt][kt][1], w0r[gt][kt][3]);
                }
            }
            int r0 = g * 64 + mt * 16 + gg;
            float x0 = xs[t * 128 + r0], x1 = xs[t * 128 + r0 + 8];
            float hv[8];
#pragma unroll
            for (int nt = 0; nt < 2; nt++)
#pragma unroll
                for (int q = 0; q < 4; q++) {
                    int e = q & 1;
                    int jb = jj + nt * 8 + tg * 2 + e;
                    float xv = (q >> 1) ? x1 : x0;
                    float gi = acc[nt * 4 + q]      + fmaf(xv, wbp[jb],       wbp[256 + jb]);
                    float gf = acc[8 + nt * 4 + q]  + fmaf(xv, wbp[64 + jb],  wbp[320 + jb]);
                    float gG = acc[16 + nt * 4 + q] + fmaf(xv, wbp[128 + jb], wbp[384 + jb]);
                    float go = acc[24 + nt * 4 + q] + fmaf(xv, wbp[192 + jb], wbp[448 + jb]);
                    float c = sig_hw(gf) * c0[mt * 8 + nt * 4 + q] + sig_hw(gi) * tanh_hw(gG);
                    c0[mt * 8 + nt * 4 + q] = c;
                    hv[nt * 4 + q] = sig_hw(go) * tanh_hw(c);
                }
#pragma unroll
            for (int nt = 0; nt < 2; nt++) {
                __half2 p0 = __floats2half2_rn(hv[nt * 4 + 0], hv[nt * 4 + 1]);
                __half2 p1 = __floats2half2_rn(hv[nt * 4 + 2], hv[nt * 4 + 3]);
                stash[mt * 4 + nt * 2 + 0] = *(uint32_t*)&p0;
                stash[mt * 4 + nt * 2 + 1] = *(uint32_t*)&p1;
            }
        }
        asm volatile("bar.sync %0, 128;" :: "r"(barid) : "memory");
#pragma unroll
        for (int mt = 0; mt < 4; mt++)
#pragma unroll
            for (int nt = 0; nt < 2; nt++) {
                int row = g * 64 + mt * 16 + gg;
                int ch = 2 * wg + nt;
                *(uint32_t*)(dsm + OFF_H + h_off(row, ch, tg))     = stash[mt * 4 + nt * 2 + 0];
                *(uint32_t*)(dsm + OFF_H + h_off(row + 8, ch, tg)) = stash[mt * 4 + nt * 2 + 1];
            }
        asm volatile("bar.sync %0, 128;" :: "r"(barid) : "memory");

        // ============ layer 1 (K=128: h0|h1, B=Wcat from SMEM) ============
#pragma unroll
        for (int mt = 0; mt < 4; mt++) {
            float acc[32];
#pragma unroll
            for (int i = 0; i < 32; i++) acc[i] = 0.f;
#pragma unroll
            for (int kt = 0; kt < 8; kt++) {
                uint32_t Ah[4];
                ldsm4(Ah, smb + OFF_H + a_off(g, mt, kt, lane));
#pragma unroll
                for (int gt = 0; gt < 4; gt++) {
                    uint32_t B[4];
                    ldsm4(B, smb + OFF_WC + bc_off(gt, jj, kt, lane));
                    mma16816(acc + gt * 8,     Ah, B[0], B[2]);
                    mma16816(acc + gt * 8 + 4, Ah, B[1], B[3]);
                }
            }
            int r0 = g * 64 + mt * 16 + gg;
            float hv[8];
#pragma unroll
            for (int nt = 0; nt < 2; nt++)
#pragma unroll
                for (int q = 0; q < 4; q++) {
                    int e = q & 1;
                    int jb = jj + nt * 8 + tg * 2 + e;
                    float gi = acc[nt * 4 + q]      + wbp[512 + jb];
                    float gf = acc[8 + nt * 4 + q]  + wbp[576 + jb];
                    float gG = acc[16 + nt * 4 + q] + wbp[640 + jb];
                    float go = acc[24 + nt * 4 + q] + wbp[704 + jb];
                    float c = sig_hw(gf) * c1[mt * 8 + nt * 4 + q] + sig_hw(gi) * tanh_hw(gG);
                    c1[mt * 8 + nt * 4 + q] = c;
                    hv[nt * 4 + q] = sig_hw(go) * tanh_hw(c);
                }
            if (t == TT - 1) {
                int nd0 = nodeBase + r0, nd1 = nd0 + 8;
#pragma unroll
                for (int nt = 0; nt < 2; nt++) {
                    int j0 = jj + nt * 8 + tg * 2;
                    if (nd0 < NN)
                        *(float2*)&g_h2last[nd0 * 64 + j0] = make_float2(hv[nt * 4 + 0], hv[nt * 4 + 1]);
                    if (nd1 < NN)
                        *(float2*)&g_h2last[nd1 * 64 + j0] = make_float2(hv[nt * 4 + 2], hv[nt * 4 + 3]);
                }
            } else {
#pragma unroll
                for (int nt = 0; nt < 2; nt++) {
                    __half2 p0 = __floats2half2_rn(hv[nt * 4 + 0], hv[nt * 4 + 1]);
                    __half2 p1 = __floats2half2_rn(hv[nt * 4 + 2], hv[nt * 4 + 3]);
                    stash[mt * 4 + nt * 2 + 0] = *(uint32_t*)&p0;
                    stash[mt * 4 + nt * 2 + 1] = *(uint32_t*)&p1;
                }
            }
        }
        if (t < TT - 1) {
            asm volatile("bar.sync %0, 128;" :: "r"(barid) : "memory");
#pragma unroll
            for (int mt = 0; mt < 4; mt++)
#pragma unroll
                for (int nt = 0; nt < 2; nt++) {
                    int row = g * 64 + mt * 16 + gg;
                    int ch = 8 + 2 * wg + nt;
                    *(uint32_t*)(dsm + OFF_H + h_off(row, ch, tg))     = stash[mt * 4 + nt * 2 + 0];
                    *(uint32_t*)(dsm + OFF_H + h_off(row + 8, ch, tg)) = stash[mt * 4 + nt * 2 + 1];
                }
            asm volatile("bar.sync %0, 128;" :: "r"(barid) : "memory");
        }
    }
}

// ---------------- K3: xl = combined @ lin_w^T ; a_src, a_dst ----------------
__global__ void node_feat_kernel(const float* __restrict__ x,
                                 const float* __restrict__ lin_w,
                                 const float* __restrict__ att_src,
                                 const float* __restrict__ att_dst) {
    __shared__ float sW[72 * 128];
    __shared__ float scomb[8][72];
    __shared__ float ssrc[128], sdst[128];
    int tid = threadIdx.x;
    for (int i = tid; i < 72 * 128; i += 256) {
        int d = i >> 7, g = i & 127;
        sW[i] = lin_w[g * 72 + d];
    }
    if (tid < 128) { ssrc[tid] = att_src[tid]; sdst[tid] = att_dst[tid]; }
    int nl = tid >> 5, lane = tid & 31;
    int node = blockIdx.x * 8 + nl;
    for (int d = lane; d < 72; d += 32)
        scomb[nl][d] = (node < NN) ? (d < 64 ? g_h2last[node * 64 + d]
                                             : x[node * 32 + (d - 64)])
                                   : 0.f;
    __syncthreads();
    float o0 = 0.f, o1 = 0.f, o2 = 0.f, o3 = 0.f;
    for (int d = 0; d < 72; d++) {
        float cv = scomb[nl][d];
        const float4 w4 = *(const float4*)&sW[d * 128 + lane * 4];
        o0 += cv * w4.x; o1 += cv * w4.y; o2 += cv * w4.z; o3 += cv * w4.w;
    }
    float ps = o0 * ssrc[lane * 4] + o1 * ssrc[lane * 4 + 1] +
               o2 * ssrc[lane * 4 + 2] + o3 * ssrc[lane * 4 + 3];
    float pd = o0 * sdst[lane * 4] + o1 * sdst[lane * 4 + 1] +
               o2 * sdst[lane * 4 + 2] + o3 * sdst[lane * 4 + 3];
    for (int off = 4; off; off >>= 1) {
        ps += __shfl_down_sync(0xffffffffu, ps, off, 8);
        pd += __shfl_down_sync(0xffffffffu, pd, off, 8);
    }
    if (node < NN) {
        *(float4*)&g_xl[node * 128 + lane * 4] = make_float4(o0, o1, o2, o3);
        if ((lane & 7) == 0) {
            int h = lane >> 3;
            g_asrc[node * 4 + h] = ps;
            g_adst[node * 4 + h] = pd;
        }
    }
}

// ---------------- per-edge logit ----------------
__device__ __forceinline__ void edge_logits(const void* ei, const float* ea,
                                            long long e, long long& s, long long& d,
                                            float lg[4]) {
    float a;
    if (e < EE) {
        s = eidx(ei, e);
        d = eidx(ei, (long long)EE + e);
        a = ea[e];
    } else {
        s = d = e - EE;
        a = g_meansum * (1.f / EE);
    }
    const float4 as = *(const float4*)&g_asrc[s * 4];
    const float4 ad = *(const float4*)&g_adst[d * 4];
    const float4 Kv = *(const float4*)g_K;
    lg[0] = as.x + ad.x + a * Kv.x;
    lg[1] = as.y + ad.y + a * Kv.y;
    lg[2] = as.z + ad.z + a * Kv.z;
    lg[3] = as.w + ad.w + a * Kv.w;
#pragma unroll
    for (int h = 0; h < 4; h++) lg[h] = lg[h] > 0.f ? lg[h] : 0.2f * lg[h];
}

// ---------------- K4: segment max (caches logits into g_ex) ----------------
__global__ void logit_max_kernel(const void* __restrict__ ei, const float* __restrict__ ea) {
    long long e = (long long)blockIdx.x * blockDim.x + threadIdx.x;
    if (e >= ETOT) return;
    long long s, d;
    float lg[4];
    edge_logits(ei, ea, e, s, d, lg);
    *(float4*)&g_ex[e * 4] = make_float4(lg[0], lg[1], lg[2], lg[3]);
#pragma unroll
    for (int h = 0; h < 4; h++) atomicMaxF(&g_max[d * 4 + h], lg[h]);
}

// ---------------- K5: ex + denom ----------------
__global__ void softmax_kernel(const void* __restrict__ ei) {
    long long e = (long long)blockIdx.x * blockDim.x + threadIdx.x;
    if (e >= ETOT) return;
    long long d = (e < EE) ? eidx(ei, (long long)EE + e) : (e - EE);
    const float4 lg = *(const float4*)&g_ex[e * 4];
    const float4 mv = *(const float4*)&g_max[d * 4];
    float e0 = __expf(lg.x - mv.x);
    float e1 = __expf(lg.y - mv.y);
    float e2 = __expf(lg.z - mv.z);
    float e3 = __expf(lg.w - mv.w);
    *(float4*)&g_ex[e * 4] = make_float4(e0, e1, e2, e3);
    float* dptr = &g_denom[d * 4];
    asm volatile("red.global.add.v4.f32 [%0], {%1,%2,%3,%4};"
                 :: "l"(dptr), "f"(e0), "f"(e1), "f"(e2), "f"(e3) : "memory");
}

// ---------------- K6: message scatter ----------------
__global__ void message_kernel(const void* __restrict__ ei) {
    long long idx = (long long)blockIdx.x * blockDim.x + threadIdx.x;
    long long e = idx >> 5;
    int lane = (int)(idx & 31);
    if (e >= ETOT) return;
    long long s, d;
    if (e < EE) {
        s = eidx(ei, e);
        d = eidx(ei, (long long)EE + e);
    } else {
        s = d = e - EE;
    }
    int h = lane >> 3;
    float ex = g_ex[e * 4 + h];
    float dn = g_denom[d * 4 + h];
    float al = ex / (dn + 1e-16f);
    float4 xv = ((const float4*)(g_xl + s * 128))[lane];
    float* dst = g_accum + d * 128 + lane * 4;
    asm volatile("red.global.add.v4.f32 [%0], {%1,%2,%3,%4};"
                 :: "l"(dst), "f"(xv.x * al), "f"(xv.y * al),
                    "f"(xv.z * al), "f"(xv.w * al) : "memory");
}

// ---------------- K7: bias + elu + fc + relu ----------------
__global__ void out_kernel(const float* __restrict__ gat_bias,
                           const float* __restrict__ fc_w,
                           const float* __restrict__ fc_b,
                           float* __restrict__ out) {
    long long idx = (long long)blockIdx.x * blockDim.x + threadIdx.x;
    int node = (int)(idx >> 5), lane = (int)(idx & 31);
    if (node >= NN) return;
    float a0 = 0.f, a1 = 0.f, a2 = 0.f, a3 = 0.f;
    const float4 av = *(const float4*)&g_accum[node * 128 + lane * 4];
    const float4 bv = *(const float4*)&gat_bias[lane * 4];
    float v[4] = {av.x + bv.x, av.y + bv.y, av.z + bv.z, av.w + bv.w};
#pragma unroll
    for (int r = 0; r < 4; r++) {
        float vv = v[r] > 0.f ? v[r] : expm1f(v[r]);
        int hc = lane * 4 + r;
        a0 += vv * fc_w[0 * 128 + hc];
        a1 += vv * fc_w[1 * 128 + hc];
        a2 += vv * fc_w[2 * 128 + hc];
        a3 += vv * fc_w[3 * 128 + hc];
    }
    for (int off = 16; off; off >>= 1) {
        a0 += __shfl_down_sync(0xffffffffu, a0, off);
        a1 += __shfl_down_sync(0xffffffffu, a1, off);
        a2 += __shfl_down_sync(0xffffffffu, a2, off);
        a3 += __shfl_down_sync(0xffffffffu, a3, off);
    }
    if (lane == 0) {
        out[node * 4 + 0] = fmaxf(a0 + fc_b[0], 0.f);
        out[node * 4 + 1] = fmaxf(a1 + fc_b[1], 0.f);
        out[node * 4 + 2] = fmaxf(a2 + fc_b[2], 0.f);
        out[node * 4 + 3] = fmaxf(a3 + fc_b[3], 0.f);
    }
}

// ---------------- launch ----------------
extern "C" void kernel_launch(void* const* d_in, const int* in_sizes, int n_in,
                              void* d_out, int out_size) {
    const float* x        = (const float*)d_in[0];
    const void*  ei       = d_in[1];
    const float* ea       = (const float*)d_in[2];
    const float* w_ih0    = (const float*)d_in[3];
    const float* w_hh0    = (const float*)d_in[4];
    const float* b_ih0    = (const float*)d_in[5];
    const float* b_hh0    = (const float*)d_in[6];
    const float* w_ih1    = (const float*)d_in[7];
    const float* w_hh1    = (const float*)d_in[8];
    const float* b_ih1    = (const float*)d_in[9];
    const float* b_hh1    = (const float*)d_in[10];
    const float* lin_w    = (const float*)d_in[11];
    const float* lin_ew   = (const float*)d_in[12];
    const float* att_src  = (const float*)d_in[13];
    const float* att_dst  = (const float*)d_in[14];
    const float* att_edge = (const float*)d_in[15];
    const float* gat_bias = (const float*)d_in[16];
    const float* fc_w     = (const float*)d_in[17];
    const float* fc_b     = (const float*)d_in[18];
    float* out = (float*)d_out;

    cudaFuncSetAttribute(lstm_mma_kernel, cudaFuncAttributeMaxDynamicSharedMemorySize,
                         LSTM_DSMEM);

    init_kernel<<<2048, 256>>>(lin_ew, att_edge);
    detect_kernel<<<1, 32>>>((const long long*)ei);
    mean_kernel<<<256, 256>>>(ea);
    lstm_mma_kernel<<<(NN + 127) / 128, 256, LSTM_DSMEM>>>(
        x, w_ih0, w_hh0, b_ih0, b_hh0, w_ih1, w_hh1, b_ih1, b_hh1);
    node_feat_kernel<<<(NN + 7) / 8, 256>>>(x, lin_w, att_src, att_dst);
    logit_max_kernel<<<(ETOT + 255) / 256, 256>>>(ei, ea);
    softmax_kernel<<<(ETOT + 255) / 256, 256>>>(ei);
    message_kernel<<<(int)(((long long)ETOT * 32 + 255) / 256), 256>>>(ei);
    out_kernel<<<(NN * 32 + 255) / 256, 256>>>(gat_bias, fc_w, fc_b, out);
}